// round 12
// baseline (speedup 1.0000x reference)
#include <cuda_runtime.h>
#include <cstdint>

#define S_LEN   4096
#define DMODEL  1024
#define HEADS   16
#define DKV     64
#define LOG2E   1.4426950408889634f

// ---------------- scratch ---------------------------------------------------
__device__ float    g_att[S_LEN * DMODEL];       // fp32 [s, h*64+d]
__device__ uint32_t g_wqh[512 * 1024], g_wql[512 * 1024];
__device__ uint32_t g_wkh[512 * 64],   g_wkl[512 * 64];
__device__ uint32_t g_wvh[512 * 64],   g_wvl[512 * 64];
__device__ uint32_t g_woh[512 * 1024], g_wol[512 * 1024];
__device__ uint32_t g_qph[S_LEN * 512], g_qpl[S_LEN * 512];   // fp16 pairs (scaled by log2e)
__device__ uint32_t g_kp[S_LEN * 32];                          // fp16 pairs [key][dk-pair]
__device__ uint32_t g_vth[64 * (S_LEN / 2)], g_vtl[64 * (S_LEN / 2)]; // bf16 [dk][key-pair]

// ---------------- numeric helpers -------------------------------------------
__device__ __forceinline__ void split2(float x, float y, uint32_t& h, uint32_t& l) {
    uint32_t hp;
    asm("cvt.rn.bf16x2.f32 %0,%1,%2;" : "=r"(hp) : "f"(y), "f"(x));
    float hx = __uint_as_float(hp << 16);
    float hy = __uint_as_float(hp & 0xffff0000u);
    asm("cvt.rn.bf16x2.f32 %0,%1,%2;" : "=r"(l) : "f"(y - hy), "f"(x - hx));
    h = hp;
}
__device__ __forceinline__ void splitf16(float x, float y, uint32_t& h, uint32_t& l) {
    uint32_t hp;
    asm("cvt.rn.f16x2.f32 %0,%1,%2;" : "=r"(hp) : "f"(y), "f"(x));
    float hx, hy;
    asm("{.reg .f16 a,b; mov.b32 {a,b},%2; cvt.f32.f16 %0,a; cvt.f32.f16 %1,b;}"
        : "=f"(hx), "=f"(hy) : "r"(hp));
    asm("cvt.rn.f16x2.f32 %0,%1,%2;" : "=r"(l) : "f"(y - hy), "f"(x - hx));
    h = hp;
}
__device__ __forceinline__ uint32_t packf16(float x, float y) {
    uint32_t r;
    asm("cvt.rn.f16x2.f32 %0,%1,%2;" : "=r"(r) : "f"(y), "f"(x));
    return r;
}
__device__ __forceinline__ float ex2f(float x) {
    float r;
    asm("ex2.approx.f32 %0,%1;" : "=f"(r) : "f"(x));
    return r;
}
__device__ __forceinline__ void mma_bf16(float* d, const uint32_t* a,
                                         uint32_t b0, uint32_t b1) {
    asm volatile("mma.sync.aligned.m16n8k16.row.col.f32.bf16.bf16.f32 "
        "{%0,%1,%2,%3},{%4,%5,%6,%7},{%8,%9},{%0,%1,%2,%3};"
        : "+f"(d[0]), "+f"(d[1]), "+f"(d[2]), "+f"(d[3])
        : "r"(a[0]), "r"(a[1]), "r"(a[2]), "r"(a[3]), "r"(b0), "r"(b1));
}
__device__ __forceinline__ void mma_f16(float* d, const uint32_t* a,
                                        uint32_t b0, uint32_t b1) {
    asm volatile("mma.sync.aligned.m16n8k16.row.col.f32.f16.f16.f32 "
        "{%0,%1,%2,%3},{%4,%5,%6,%7},{%8,%9},{%0,%1,%2,%3};"
        : "+f"(d[0]), "+f"(d[1]), "+f"(d[2]), "+f"(d[3])
        : "r"(a[0]), "r"(a[1]), "r"(a[2]), "r"(a[3]), "r"(b0), "r"(b1));
}
__device__ __forceinline__ void ldsm4(uint32_t& r0, uint32_t& r1,
                                      uint32_t& r2, uint32_t& r3, uint32_t addr) {
    asm volatile("ldmatrix.sync.aligned.m8n8.x4.shared.b16 {%0,%1,%2,%3}, [%4];"
                 : "=r"(r0), "=r"(r1), "=r"(r2), "=r"(r3) : "r"(addr));
}
__device__ __forceinline__ uint32_t smem_u32(const void* p) {
    uint32_t a;
    asm("{ .reg .u64 t; cvta.to.shared.u64 t, %1; cvt.u32.u64 %0, t; }"
        : "=r"(a) : "l"(p));
    return a;
}
__device__ __forceinline__ void cp16(uint32_t saddr, const void* g) {
    asm volatile("cp.async.cg.shared.global [%0], [%1], 16;" :: "r"(saddr), "l"(g));
}
#define CP_COMMIT() asm volatile("cp.async.commit_group;" ::: "memory")
#define CP_WAIT0()  asm volatile("cp.async.wait_group 0;"  ::: "memory")

// ---------------- combined weight pre-split (bf16 h/l for GEMM B) -----------
__global__ __launch_bounds__(256)
void splitAll(const float* __restrict__ Wq, const float* __restrict__ Wo,
              const float* __restrict__ Wk, const float* __restrict__ Wv,
              uint32_t* __restrict__ wqh, uint32_t* __restrict__ wql,
              uint32_t* __restrict__ woh, uint32_t* __restrict__ wol,
              uint32_t* __restrict__ wkh, uint32_t* __restrict__ wkl,
              uint32_t* __restrict__ wvh, uint32_t* __restrict__ wvl)
{
    constexpr int BIG = 512 * 1024, SMALL = 512 * 64;
    int idx = blockIdx.x * 256 + threadIdx.x;
    const float* W; uint32_t *Wh, *Wl; int i, N;
    if (idx < BIG)               { W = Wq; Wh = wqh; Wl = wql; i = idx;            N = 1024; }
    else if (idx < 2 * BIG)      { W = Wo; Wh = woh; Wl = wol; i = idx - BIG;      N = 1024; }
    else if (idx < 2 * BIG + SMALL) { W = Wk; Wh = wkh; Wl = wkl; i = idx - 2*BIG; N = 64; }
    else if (idx < 2 * BIG + 2 * SMALL) { W = Wv; Wh = wvh; Wl = wvl; i = idx - 2*BIG - SMALL; N = 64; }
    else return;
    int kp = i / N, n = i - kp * N;
    float a = W[(size_t)(2 * kp) * N + n];
    float b = W[(size_t)(2 * kp + 1) * N + n];
    uint32_t h, l;
    split2(a, b, h, l);
    Wh[i] = h; Wl[i] = l;
}

// ---------------- bf16x3 GEMM, cp.async double-buffered, LDSM A -------------
// CMODE 0: C fp32.
// CMODE 3: fused K/V proj — blockIdx.x 0: K fp16-pair epilogue; 1: V-transposed.
// CMODE 4: Q-proj epilogue — scale by LOG2E, fp16 hi/lo pairs -> Ch/Cl.
template<int BM, int BN, int BK, int WARPS_M, int WARPS_N, int CMODE>
__global__ __launch_bounds__(WARPS_M * WARPS_N * 32)
void bgemm3(const float* __restrict__ A, const uint32_t* __restrict__ Bh,
            const uint32_t* __restrict__ Bl, const float* __restrict__ bias,
            float* __restrict__ C, uint32_t* __restrict__ Ch,
            uint32_t* __restrict__ Cl,
            const float* __restrict__ A2, const uint32_t* __restrict__ Bh2,
            const uint32_t* __restrict__ Bl2, const float* __restrict__ bias2,
            uint32_t* __restrict__ Ch2, uint32_t* __restrict__ Cl2,
            int M, int N, int K)
{
    constexpr int THREADS = WARPS_M * WARPS_N * 32;
    constexpr int WM = BM / WARPS_M, WN = BN / WARPS_N;
    constexpr int MT = WM / 16, NT = WN / 8;
    constexpr int KW = BK / 2;
    constexpr int AW = KW + 4;       // 20 words ≡ 20 mod 32: ldsm rows conflict-free
    constexpr int BW = BN + 8;
    constexpr int ASZ = BM * AW;
    constexpr int BSZ = KW * BW;
    constexpr int A_IT = BM * BK / (4 * THREADS);
    constexpr int B_IT = KW * (BN / 4) / THREADS;

    extern __shared__ uint32_t smw[];
    uint32_t* AshB = smw;
    uint32_t* AslB = smw + 2 * ASZ;
    uint32_t* BshB = smw + 4 * ASZ;
    uint32_t* BslB = smw + 4 * ASZ + 2 * BSZ;
    const uint32_t sm_base = smem_u32(smw);
    const uint32_t sm_bsh = smem_u32(BshB);
    const uint32_t sm_bsl = smem_u32(BslB);

    bool isV = false;
    if constexpr (CMODE == 3) {
        if (blockIdx.x == 1) {
            isV = true;
            A = A2; Bh = Bh2; Bl = Bl2; bias = bias2; Ch = Ch2; Cl = Cl2;
        }
    }

    const int tid  = threadIdx.x;
    const int warp = tid >> 5, lane = tid & 31;
    const int g = lane >> 2, q = lane & 3;
    const int lt = lane >> 3, lr = lane & 7;
    const int wm = warp / WARPS_N, wn = warp % WARPS_N;
    const int m0 = blockIdx.y * BM;
    const int n0 = (CMODE == 3) ? 0 : blockIdx.x * BN;

    float acc[MT][NT][4];
    #pragma unroll
    for (int i = 0; i < MT; i++)
        #pragma unroll
        for (int j = 0; j < NT; j++)
            #pragma unroll
            for (int e = 0; e < 4; e++) acc[i][j][e] = 0.f;

    float4 aPF[A_IT];

    auto loadA = [&](int k0) {
        #pragma unroll
        for (int i = 0; i < A_IT; i++) {
            int flat = tid + i * THREADS;
            int r = flat / (BK / 4), c = (flat % (BK / 4)) * 4;
            aPF[i] = *(const float4*)(A + (size_t)(m0 + r) * K + k0 + c);
        }
    };
    auto cpB = [&](int k0, int b) {
        int kp0 = k0 / 2;
        #pragma unroll
        for (int i = 0; i < B_IT; i++) {
            int flat = tid + i * THREADS;
            int kp2 = flat / (BN / 4), c = (flat % (BN / 4)) * 4;
            uint32_t off = (uint32_t)((b * BSZ + kp2 * BW + c) * 4);
            cp16(sm_bsh + off, Bh + (size_t)(kp0 + kp2) * N + n0 + c);
            cp16(sm_bsl + off, Bl + (size_t)(kp0 + kp2) * N + n0 + c);
        }
        CP_COMMIT();
    };
    auto storeA = [&](int b) {
        uint32_t* Ash = AshB + b * ASZ;
        uint32_t* Asl = AslB + b * ASZ;
        #pragma unroll
        for (int i = 0; i < A_IT; i++) {
            int flat = tid + i * THREADS;
            int r = flat / (BK / 4), c = (flat % (BK / 4)) * 4;
            uint32_t h0, l0, h1, l1;
            split2(aPF[i].x, aPF[i].y, h0, l0);
            split2(aPF[i].z, aPF[i].w, h1, l1);
            Ash[r * AW + c / 2] = h0; Ash[r * AW + c / 2 + 1] = h1;
            Asl[r * AW + c / 2] = l0; Asl[r * AW + c / 2 + 1] = l1;
        }
    };

    loadA(0);
    cpB(0, 0);
    storeA(0);
    CP_WAIT0();
    __syncthreads();

    for (int k0 = 0; k0 < K; k0 += BK) {
        const int b = (k0 / BK) & 1;
        const bool more = (k0 + BK < K);
        if (more) { loadA(k0 + BK); cpB(k0 + BK, b ^ 1); }

        const uint32_t ash_b = sm_base + (uint32_t)((b * ASZ) * 4);
        const uint32_t asl_b = sm_base + (uint32_t)((2 * ASZ + b * ASZ) * 4);
        const uint32_t* Bsh = BshB + b * BSZ;
        const uint32_t* Bsl = BslB + b * BSZ;

        #pragma unroll
        for (int kk = 0; kk < 2; kk++) {
            const int wof = kk * 8;
            uint32_t Ah[MT][4], Al[MT][4], Bfh[NT][2], Bfl[NT][2];
            #pragma unroll
            for (int i = 0; i < MT; i++) {
                int mr = wm * WM + i * 16;
                uint32_t aoff = (uint32_t)(((mr + 8 * (lt & 1) + lr) * AW
                                           + wof + 4 * (lt >> 1)) * 4);
                ldsm4(Ah[i][0], Ah[i][1], Ah[i][2], Ah[i][3], ash_b + aoff);
                ldsm4(Al[i][0], Al[i][1], Al[i][2], Al[i][3], asl_b + aoff);
            }
            #pragma unroll
            for (int j = 0; j < NT; j++) {
                int nc = wn * WN + j * 8 + g;
                Bfh[j][0] = Bsh[(wof + q) * BW + nc];
                Bfh[j][1] = Bsh[(wof + q + 4) * BW + nc];
                Bfl[j][0] = Bsl[(wof + q) * BW + nc];
                Bfl[j][1] = Bsl[(wof + q + 4) * BW + nc];
            }
            #pragma unroll
            for (int i = 0; i < MT; i++)
                #pragma unroll
                for (int j = 0; j < NT; j++)
                    mma_bf16(acc[i][j], Ah[i], Bfh[j][0], Bfh[j][1]);
            #pragma unroll
            for (int i = 0; i < MT; i++)
                #pragma unroll
                for (int j = 0; j < NT; j++)
                    mma_bf16(acc[i][j], Ah[i], Bfl[j][0], Bfl[j][1]);
            #pragma unroll
            for (int i = 0; i < MT; i++)
                #pragma unroll
                for (int j = 0; j < NT; j++)
                    mma_bf16(acc[i][j], Al[i], Bfh[j][0], Bfh[j][1]);
        }

        if (more) storeA(b ^ 1);
        CP_WAIT0();
        __syncthreads();
    }

    const unsigned FULL = 0xffffffffu;
    #pragma unroll
    for (int i = 0; i < MT; i++) {
        int row0 = m0 + wm * WM + i * 16 + g;
        #pragma unroll
        for (int j = 0; j < NT; j++) {
            int col = n0 + wn * WN + j * 8 + 2 * q;
            float bx = bias[col], by = bias[col + 1];
            float v0 = acc[i][j][0] + bx, v1 = acc[i][j][1] + by;
            float v2 = acc[i][j][2] + bx, v3 = acc[i][j][3] + by;
            if constexpr (CMODE == 0) {
                float2 w0 = { v0, v1 }, w1 = { v2, v3 };
                *(float2*)(C + (size_t)row0 * N + col) = w0;
                *(float2*)(C + (size_t)(row0 + 8) * N + col) = w1;
            } else if constexpr (CMODE == 4) {
                v0 *= LOG2E; v1 *= LOG2E; v2 *= LOG2E; v3 *= LOG2E;
                uint32_t h, l;
                splitf16(v0, v1, h, l);
                Ch[(size_t)row0 * (N / 2) + col / 2] = h;
                Cl[(size_t)row0 * (N / 2) + col / 2] = l;
                splitf16(v2, v3, h, l);
                Ch[(size_t)(row0 + 8) * (N / 2) + col / 2] = h;
                Cl[(size_t)(row0 + 8) * (N / 2) + col / 2] = l;
            } else {
                if (!isV) {
                    Ch[(size_t)row0 * (N / 2) + col / 2] = packf16(v0, v1);
                    Ch[(size_t)(row0 + 8) * (N / 2) + col / 2] = packf16(v2, v3);
                } else {
                    float p0 = __shfl_xor_sync(FULL, v0, 4);
                    float p1 = __shfl_xor_sync(FULL, v1, 4);
                    float p2 = __shfl_xor_sync(FULL, v2, 4);
                    float p3 = __shfl_xor_sync(FULL, v3, 4);
                    uint32_t h, l;
                    if ((g & 1) == 0) {
                        split2(v0, p0, h, l);
                        Ch[(size_t)col * (S_LEN / 2) + row0 / 2] = h;
                        Cl[(size_t)col * (S_LEN / 2) + row0 / 2] = l;
                        split2(v2, p2, h, l);
                        Ch[(size_t)col * (S_LEN / 2) + (row0 + 8) / 2] = h;
                        Cl[(size_t)col * (S_LEN / 2) + (row0 + 8) / 2] = l;
                    } else {
                        split2(p1, v1, h, l);
                        Ch[(size_t)(col + 1) * (S_LEN / 2) + (row0 - 1) / 2] = h;
                        Cl[(size_t)(col + 1) * (S_LEN / 2) + (row0 - 1) / 2] = l;
                        split2(p3, v3, h, l);
                        Ch[(size_t)(col + 1) * (S_LEN / 2) + (row0 + 7) / 2] = h;
                        Cl[(size_t)(col + 1) * (S_LEN / 2) + (row0 + 7) / 2] = l;
                    }
                }
            }
        }
    }
}

// ---------------- flash MQA attention (4-chain S, Ql in smem) ---------------
// smem: 2 buffers x [K 9216 | VH 9216 | VL 9216]; QH 18432 (init only) + QL 18432.
#define PW   36
#define BUFB 27648
#define QH_OFF 55296
#define QL_OFF 73728
#define ATTN_SMEM 92160

__global__ __launch_bounds__(256, 2)
void mqa_attn_d(const uint32_t* __restrict__ qph, const uint32_t* __restrict__ qpl,
                const uint32_t* __restrict__ kp,
                const uint32_t* __restrict__ vth, const uint32_t* __restrict__ vtl,
                float* __restrict__ out)
{
    extern __shared__ char smraw[];
    const uint32_t smb = smem_u32(smraw);
    const int tid  = threadIdx.x;
    const int warp = tid >> 5, lane = tid & 31;
    const int gl = lane >> 2, q = lane & 3;
    const int lt = lane >> 3, lr = lane & 7;
    const int head = blockIdx.y;
    const int q0 = blockIdx.x * 128;
    const unsigned FULL = 0xffffffffu;

    // ---- stage packed Q (fp16, log2e-scaled): hi + lo ----
    #pragma unroll
    for (int i = 0; i < 4; i++) {
        int idx = tid + i * 256;
        int r = idx >> 3, c4 = (idx & 7) * 4;
        *(uint4*)(smraw + QH_OFF + (r * PW + c4) * 4) =
            *(const uint4*)(qph + (size_t)(q0 + r) * 512 + head * 32 + c4);
        *(uint4*)(smraw + QL_OFF + (r * PW + c4) * 4) =
            *(const uint4*)(qpl + (size_t)(q0 + r) * 512 + head * 32 + c4);
    }

    // ---- async K/V chunk load ----
    const int kkey = tid >> 2, kw0 = (tid & 3) * 8;
    auto loadKV = [&](int k0, int bb) {
        uint32_t base = smb + (uint32_t)bb + (kkey * PW + kw0) * 4;
        const uint32_t* ph = kp + (size_t)(k0 + kkey) * 32 + kw0;
        cp16(base,      ph);
        cp16(base + 16, ph + 4);
        const uint32_t* vh = vth + (size_t)kkey * (S_LEN / 2) + (k0 >> 1) + kw0;
        const uint32_t* vl = vtl + (size_t)kkey * (S_LEN / 2) + (k0 >> 1) + kw0;
        cp16(base + 9216,       vh);
        cp16(base + 9216 + 16,  vh + 4);
        cp16(base + 18432,      vl);
        cp16(base + 18432 + 16, vl + 4);
        CP_COMMIT();
    };

    loadKV(0, 0);
    __syncthreads();   // Q stores visible

    // ---- Qh fragments persistent in registers; Ql stays in smem ----
    const uint32_t qrow_off =
        (uint32_t)(((warp * 16 + 8 * (lt & 1) + lr) * PW + 4 * (lt >> 1)) * 4);
    uint32_t Qh[4][4];
    #pragma unroll
    for (int s = 0; s < 4; s++)
        ldsm4(Qh[s][0], Qh[s][1], Qh[s][2], Qh[s][3],
              smb + QH_OFF + qrow_off + s * 32);
    CP_WAIT0();
    __syncthreads();

    float O[8][4];
    #pragma unroll
    for (int j = 0; j < 8; j++)
        #pragma unroll
        for (int e = 0; e < 4; e++) O[j][e] = 0.f;
    float ls0 = 0.f, ls1 = 0.f;

    float Sfc[2][2][2][4];   // [slot][jj][chain][elem] — 4 independent chains

    auto issueS = [&](int bb, int g, int slot) {
        uint32_t kf[2][8];
        uint32_t krow = (uint32_t)(16 * g + 8 * (lt >> 1) + lr);
        #pragma unroll
        for (int s = 0; s < 4; s++) {
            uint32_t aoff = (krow * PW + 8 * s + 4 * (lt & 1)) * 4;
            ldsm4(kf[0][2*s], kf[0][2*s+1], kf[1][2*s], kf[1][2*s+1],
                  smb + bb + aoff);
        }
        #pragma unroll
        for (int jj = 0; jj < 2; jj++)
            #pragma unroll
            for (int ch = 0; ch < 2; ch++)
                #pragma unroll
                for (int e = 0; e < 4; e++) Sfc[slot][jj][ch][e] = 0.f;
        // pass 1: Qh x K   (chains ch = s&1)
        #pragma unroll
        for (int s = 0; s < 4; s++)
            #pragma unroll
            for (int jj = 0; jj < 2; jj++)
                mma_f16(Sfc[slot][jj][s & 1], Qh[s], kf[jj][2 * s], kf[jj][2 * s + 1]);
        // pass 2: Ql x K   (Ql fragments loaded fresh from smem)
        uint32_t Qlf[4][4];
        #pragma unroll
        for (int s = 0; s < 4; s++)
            ldsm4(Qlf[s][0], Qlf[s][1], Qlf[s][2], Qlf[s][3],
                  smb + QL_OFF + qrow_off + s * 32);
        #pragma unroll
        for (int s = 0; s < 4; s++)
            #pragma unroll
            for (int jj = 0; jj < 2; jj++)
                mma_f16(Sfc[slot][jj][s & 1], Qlf[s], kf[jj][2 * s], kf[jj][2 * s + 1]);
    };

    auto epiPV = [&](int bb, int g, int slot) {
        float ev[2][4];
        #pragma unroll
        for (int jj = 0; jj < 2; jj++)
            #pragma unroll
            for (int e = 0; e < 4; e++)
                ev[jj][e] = ex2f(Sfc[slot][jj][0][e] + Sfc[slot][jj][1][e]);
        #pragma unroll
        for (int jj = 0; jj < 2; jj++) {
            ls0 += ev[jj][0] + ev[jj][1];
            ls1 += ev[jj][2] + ev[jj][3];
        }
        uint32_t Ph[4], Pl[4];
        split2(ev[0][0], ev[0][1], Ph[0], Pl[0]);
        split2(ev[0][2], ev[0][3], Ph[1], Pl[1]);
        split2(ev[1][0], ev[1][1], Ph[2], Pl[2]);
        split2(ev[1][2], ev[1][3], Ph[3], Pl[3]);
        uint32_t vh[16], vl[16];
        #pragma unroll
        for (int c = 0; c < 4; c++) {
            uint32_t vrow = (uint32_t)(8 * (2 * c + (lt >> 1)) + lr);
            uint32_t aoff = (vrow * PW + 8 * g + 4 * (lt & 1)) * 4;
            ldsm4(vh[4*c], vh[4*c+1], vh[4*c+2], vh[4*c+3],
                  smb + bb + 9216 + aoff);
            ldsm4(vl[4*c], vl[4*c+1], vl[4*c+2], vl[4*c+3],
                  smb + bb + 18432 + aoff);
        }
        #pragma unroll
        for (int jv = 0; jv < 8; jv++) mma_bf16(O[jv], Ph, vh[2 * jv], vh[2 * jv + 1]);
        #pragma unroll
        for (int jv = 0; jv < 8; jv++) mma_bf16(O[jv], Ph, vl[2 * jv], vl[2 * jv + 1]);
        #pragma unroll
        for (int jv = 0; jv < 8; jv++) mma_bf16(O[jv], Pl, vh[2 * jv], vh[2 * jv + 1]);
    };

    for (int ci = 0; ci < S_LEN / 64; ci++) {
        const int bb = (ci & 1) * BUFB;
        if (ci < S_LEN / 64 - 1) loadKV((ci + 1) * 64, bb ^ BUFB);
        issueS(bb, 0, 0);
        #pragma unroll
        for (int g = 0; g < 4; g++) {
            if (g < 3) issueS(bb, g + 1, (g + 1) & 1);
            epiPV(bb, g, g & 1);
        }
        CP_WAIT0();
        __syncthreads();
    }

    // final row-sum reduction and write
    ls0 += __shfl_xor_sync(FULL, ls0, 1);
    ls0 += __shfl_xor_sync(FULL, ls0, 2);
    ls1 += __shfl_xor_sync(FULL, ls1, 1);
    ls1 += __shfl_xor_sync(FULL, ls1, 2);
    float inv0 = 1.f / ls0, inv1 = 1.f / ls1;
    int row0 = q0 + warp * 16 + gl;
    #pragma unroll
    for (int j = 0; j < 8; j++) {
        int col = head * DKV + j * 8 + 2 * q;
        float2 w0 = { O[j][0] * inv0, O[j][1] * inv0 };
        float2 w1 = { O[j][2] * inv1, O[j][3] * inv1 };
        *(float2*)(out + (size_t)row0 * DMODEL + col) = w0;
        *(float2*)(out + (size_t)(row0 + 8) * DMODEL + col) = w1;
    }
}

// ---------------- launch ----------------------------------------------------
extern "C" void kernel_launch(void* const* d_in, const int* in_sizes, int n_in,
                              void* d_out, int out_size)
{
    const float* q  = (const float*)d_in[0];
    const float* k  = (const float*)d_in[1];
    const float* v  = (const float*)d_in[2];
    const float* Wq = (const float*)d_in[3];
    const float* bq = (const float*)d_in[4];
    const float* Wk = (const float*)d_in[5];
    const float* bk = (const float*)d_in[6];
    const float* Wv = (const float*)d_in[7];
    const float* bv = (const float*)d_in[8];
    const float* Wo = (const float*)d_in[9];
    const float* bo = (const float*)d_in[10];
    float* out = (float*)d_out;

    void* p;
    cudaGetSymbolAddress(&p, g_att);  float* att = (float*)p;
    cudaGetSymbolAddress(&p, g_wqh);  uint32_t* wqh = (uint32_t*)p;
    cudaGetSymbolAddress(&p, g_wql);  uint32_t* wql = (uint32_t*)p;
    cudaGetSymbolAddress(&p, g_wkh);  uint32_t* wkh = (uint32_t*)p;
    cudaGetSymbolAddress(&p, g_wkl);  uint32_t* wkl = (uint32_t*)p;
    cudaGetSymbolAddress(&p, g_wvh);  uint32_t* wvh = (uint32_t*)p;
    cudaGetSymbolAddress(&p, g_wvl);  uint32_t* wvl = (uint32_t*)p;
    cudaGetSymbolAddress(&p, g_woh);  uint32_t* woh = (uint32_t*)p;
    cudaGetSymbolAddress(&p, g_wol);  uint32_t* wol = (uint32_t*)p;
    cudaGetSymbolAddress(&p, g_qph);  uint32_t* qph = (uint32_t*)p;
    cudaGetSymbolAddress(&p, g_qpl);  uint32_t* qpl = (uint32_t*)p;
    cudaGetSymbolAddress(&p, g_kp);   uint32_t* kpp = (uint32_t*)p;
    cudaGetSymbolAddress(&p, g_vth);  uint32_t* vth = (uint32_t*)p;
    cudaGetSymbolAddress(&p, g_vtl);  uint32_t* vtl = (uint32_t*)p;

    constexpr int SM_BIG   = (4 * 128 * 20 + 4 * 16 * 136) * 4;  // 75776
    constexpr int SM_SMALL = (4 * 64 * 20 + 4 * 16 * 72) * 4;    // 38912

    cudaFuncSetAttribute((const void*)(bgemm3<128, 128, 32, 2, 4, 4>),
                         cudaFuncAttributeMaxDynamicSharedMemorySize, SM_BIG);
    cudaFuncSetAttribute((const void*)(bgemm3<128, 128, 32, 2, 4, 0>),
                         cudaFuncAttributeMaxDynamicSharedMemorySize, SM_BIG);
    cudaFuncSetAttribute((const void*)(bgemm3<64, 64, 32, 2, 4, 3>),
                         cudaFuncAttributeMaxDynamicSharedMemorySize, SM_SMALL);
    cudaFuncSetAttribute((const void*)mqa_attn_d,
                         cudaFuncAttributeMaxDynamicSharedMemorySize, ATTN_SMEM);

    // weight pre-split
    splitAll<<<(2 * 512 * 1024 + 2 * 512 * 64 + 255) / 256, 256>>>(
        Wq, Wo, Wk, Wv, wqh, wql, woh, wol, wkh, wkl, wvh, wvl);

    // Q projection (fp16 h/l, log2e-scaled epilogue)
    bgemm3<128, 128, 32, 2, 4, 4>
        <<<dim3(DMODEL / 128, S_LEN / 128), 256, SM_BIG>>>(
            q, wqh, wql, bq, nullptr, qph, qpl,
            nullptr, nullptr, nullptr, nullptr, nullptr, nullptr,
            S_LEN, DMODEL, DMODEL);
    // K + V projections fused
    bgemm3<64, 64, 32, 2, 4, 3>
        <<<dim3(2, S_LEN / 64), 256, SM_SMALL>>>(
            k, wkh, wkl, bk, nullptr, kpp, nullptr,
            v, wvh, wvl, bv, vth, vtl,
            S_LEN, DKV, DMODEL);
    // attention
    mqa_attn_d<<<dim3(S_LEN / 128, HEADS), 256, ATTN_SMEM>>>(qph, qpl, kpp,
                                                             vth, vtl, att);
    // O projection
    bgemm3<128, 128, 32, 2, 4, 0>
        <<<dim3(DMODEL / 128, S_LEN / 128), 256, SM_BIG>>>(
            att, woh, wol, bo, out, nullptr, nullptr,
            nullptr, nullptr, nullptr, nullptr, nullptr, nullptr,
            S_LEN, DMODEL, DMODEL);
}

// round 13
// speedup vs baseline: 1.0329x; 1.0329x over previous
#include <cuda_runtime.h>
#include <cstdint>

#define S_LEN   4096
#define DMODEL  1024
#define HEADS   16
#define DKV     64
#define LOG2E   1.4426950408889634f

// ---------------- scratch ---------------------------------------------------
__device__ float    g_att[S_LEN * DMODEL];       // fp32 [s, h*64+d]
__device__ uint32_t g_wqh[512 * 1024], g_wql[512 * 1024];
__device__ uint32_t g_wkh[512 * 64],   g_wkl[512 * 64];
__device__ uint32_t g_wvh[512 * 64],   g_wvl[512 * 64];
__device__ uint32_t g_woh[512 * 1024], g_wol[512 * 1024];
__device__ uint32_t g_qph[S_LEN * 512], g_qpl[S_LEN * 512];   // fp16 pairs (scaled by log2e)
__device__ uint32_t g_kp[S_LEN * 32];                          // fp16 pairs [key][dk-pair]
__device__ uint32_t g_vth[64 * (S_LEN / 2)], g_vtl[64 * (S_LEN / 2)]; // bf16 [dk][key-pair]

// ---------------- numeric helpers -------------------------------------------
__device__ __forceinline__ void split2(float x, float y, uint32_t& h, uint32_t& l) {
    uint32_t hp;
    asm("cvt.rn.bf16x2.f32 %0,%1,%2;" : "=r"(hp) : "f"(y), "f"(x));
    float hx = __uint_as_float(hp << 16);
    float hy = __uint_as_float(hp & 0xffff0000u);
    asm("cvt.rn.bf16x2.f32 %0,%1,%2;" : "=r"(l) : "f"(y - hy), "f"(x - hx));
    h = hp;
}
__device__ __forceinline__ void splitf16(float x, float y, uint32_t& h, uint32_t& l) {
    uint32_t hp;
    asm("cvt.rn.f16x2.f32 %0,%1,%2;" : "=r"(hp) : "f"(y), "f"(x));
    float hx, hy;
    asm("{.reg .f16 a,b; mov.b32 {a,b},%2; cvt.f32.f16 %0,a; cvt.f32.f16 %1,b;}"
        : "=f"(hx), "=f"(hy) : "r"(hp));
    asm("cvt.rn.f16x2.f32 %0,%1,%2;" : "=r"(l) : "f"(y - hy), "f"(x - hx));
    h = hp;
}
__device__ __forceinline__ uint32_t packf16(float x, float y) {
    uint32_t r;
    asm("cvt.rn.f16x2.f32 %0,%1,%2;" : "=r"(r) : "f"(y), "f"(x));
    return r;
}
__device__ __forceinline__ float ex2f(float x) {
    float r;
    asm("ex2.approx.f32 %0,%1;" : "=f"(r) : "f"(x));
    return r;
}
__device__ __forceinline__ void mma_bf16(float* d, const uint32_t* a,
                                         uint32_t b0, uint32_t b1) {
    asm volatile("mma.sync.aligned.m16n8k16.row.col.f32.bf16.bf16.f32 "
        "{%0,%1,%2,%3},{%4,%5,%6,%7},{%8,%9},{%0,%1,%2,%3};"
        : "+f"(d[0]), "+f"(d[1]), "+f"(d[2]), "+f"(d[3])
        : "r"(a[0]), "r"(a[1]), "r"(a[2]), "r"(a[3]), "r"(b0), "r"(b1));
}
__device__ __forceinline__ void mma_f16(float* d, const uint32_t* a,
                                        uint32_t b0, uint32_t b1) {
    asm volatile("mma.sync.aligned.m16n8k16.row.col.f32.f16.f16.f32 "
        "{%0,%1,%2,%3},{%4,%5,%6,%7},{%8,%9},{%0,%1,%2,%3};"
        : "+f"(d[0]), "+f"(d[1]), "+f"(d[2]), "+f"(d[3])
        : "r"(a[0]), "r"(a[1]), "r"(a[2]), "r"(a[3]), "r"(b0), "r"(b1));
}
__device__ __forceinline__ void ldsm4(uint32_t& r0, uint32_t& r1,
                                      uint32_t& r2, uint32_t& r3, uint32_t addr) {
    asm volatile("ldmatrix.sync.aligned.m8n8.x4.shared.b16 {%0,%1,%2,%3}, [%4];"
                 : "=r"(r0), "=r"(r1), "=r"(r2), "=r"(r3) : "r"(addr));
}
__device__ __forceinline__ uint32_t smem_u32(const void* p) {
    uint32_t a;
    asm("{ .reg .u64 t; cvta.to.shared.u64 t, %1; cvt.u32.u64 %0, t; }"
        : "=r"(a) : "l"(p));
    return a;
}
__device__ __forceinline__ void cp16(uint32_t saddr, const void* g) {
    asm volatile("cp.async.cg.shared.global [%0], [%1], 16;" :: "r"(saddr), "l"(g));
}
#define CP_COMMIT() asm volatile("cp.async.commit_group;" ::: "memory")
#define CP_WAIT0()  asm volatile("cp.async.wait_group 0;"  ::: "memory")

// ---------------- combined weight pre-split (bf16 h/l for GEMM B) -----------
__global__ __launch_bounds__(256)
void splitAll(const float* __restrict__ Wq, const float* __restrict__ Wo,
              const float* __restrict__ Wk, const float* __restrict__ Wv,
              uint32_t* __restrict__ wqh, uint32_t* __restrict__ wql,
              uint32_t* __restrict__ woh, uint32_t* __restrict__ wol,
              uint32_t* __restrict__ wkh, uint32_t* __restrict__ wkl,
              uint32_t* __restrict__ wvh, uint32_t* __restrict__ wvl)
{
    constexpr int BIG = 512 * 1024, SMALL = 512 * 64;
    int idx = blockIdx.x * 256 + threadIdx.x;
    const float* W; uint32_t *Wh, *Wl; int i, N;
    if (idx < BIG)               { W = Wq; Wh = wqh; Wl = wql; i = idx;            N = 1024; }
    else if (idx < 2 * BIG)      { W = Wo; Wh = woh; Wl = wol; i = idx - BIG;      N = 1024; }
    else if (idx < 2 * BIG + SMALL) { W = Wk; Wh = wkh; Wl = wkl; i = idx - 2*BIG; N = 64; }
    else if (idx < 2 * BIG + 2 * SMALL) { W = Wv; Wh = wvh; Wl = wvl; i = idx - 2*BIG - SMALL; N = 64; }
    else return;
    int kp = i / N, n = i - kp * N;
    float a = W[(size_t)(2 * kp) * N + n];
    float b = W[(size_t)(2 * kp + 1) * N + n];
    uint32_t h, l;
    split2(a, b, h, l);
    Wh[i] = h; Wl[i] = l;
}

// ---------------- bf16x3 GEMM, cp.async double-buffered, LDSM A -------------
// CMODE 0: C fp32.
// CMODE 3: fused K/V proj — blockIdx.x 0: K fp16-pair epilogue; 1: V-transposed.
// CMODE 4: Q-proj epilogue — scale by LOG2E, fp16 hi/lo pairs -> Ch/Cl.
template<int BM, int BN, int BK, int WARPS_M, int WARPS_N, int CMODE>
__global__ __launch_bounds__(WARPS_M * WARPS_N * 32)
void bgemm3(const float* __restrict__ A, const uint32_t* __restrict__ Bh,
            const uint32_t* __restrict__ Bl, const float* __restrict__ bias,
            float* __restrict__ C, uint32_t* __restrict__ Ch,
            uint32_t* __restrict__ Cl,
            const float* __restrict__ A2, const uint32_t* __restrict__ Bh2,
            const uint32_t* __restrict__ Bl2, const float* __restrict__ bias2,
            uint32_t* __restrict__ Ch2, uint32_t* __restrict__ Cl2,
            int M, int N, int K)
{
    constexpr int THREADS = WARPS_M * WARPS_N * 32;
    constexpr int WM = BM / WARPS_M, WN = BN / WARPS_N;
    constexpr int MT = WM / 16, NT = WN / 8;
    constexpr int KW = BK / 2;
    constexpr int AW = KW + 4;       // 20 words: ldsm rows conflict-free
    constexpr int BW = BN + 8;
    constexpr int ASZ = BM * AW;
    constexpr int BSZ = KW * BW;
    constexpr int A_IT = BM * BK / (4 * THREADS);
    constexpr int B_IT = KW * (BN / 4) / THREADS;

    extern __shared__ uint32_t smw[];
    uint32_t* AshB = smw;
    uint32_t* AslB = smw + 2 * ASZ;
    uint32_t* BshB = smw + 4 * ASZ;
    uint32_t* BslB = smw + 4 * ASZ + 2 * BSZ;
    const uint32_t sm_base = smem_u32(smw);
    const uint32_t sm_bsh = smem_u32(BshB);
    const uint32_t sm_bsl = smem_u32(BslB);

    bool isV = false;
    if constexpr (CMODE == 3) {
        if (blockIdx.x == 1) {
            isV = true;
            A = A2; Bh = Bh2; Bl = Bl2; bias = bias2; Ch = Ch2; Cl = Cl2;
        }
    }

    const int tid  = threadIdx.x;
    const int warp = tid >> 5, lane = tid & 31;
    const int g = lane >> 2, q = lane & 3;
    const int lt = lane >> 3, lr = lane & 7;
    const int wm = warp / WARPS_N, wn = warp % WARPS_N;
    const int m0 = blockIdx.y * BM;
    const int n0 = (CMODE == 3) ? 0 : blockIdx.x * BN;

    float acc[MT][NT][4];
    #pragma unroll
    for (int i = 0; i < MT; i++)
        #pragma unroll
        for (int j = 0; j < NT; j++)
            #pragma unroll
            for (int e = 0; e < 4; e++) acc[i][j][e] = 0.f;

    float4 aPF[A_IT];

    auto loadA = [&](int k0) {
        #pragma unroll
        for (int i = 0; i < A_IT; i++) {
            int flat = tid + i * THREADS;
            int r = flat / (BK / 4), c = (flat % (BK / 4)) * 4;
            aPF[i] = *(const float4*)(A + (size_t)(m0 + r) * K + k0 + c);
        }
    };
    auto cpB = [&](int k0, int b) {
        int kp0 = k0 / 2;
        #pragma unroll
        for (int i = 0; i < B_IT; i++) {
            int flat = tid + i * THREADS;
            int kp2 = flat / (BN / 4), c = (flat % (BN / 4)) * 4;
            uint32_t off = (uint32_t)((b * BSZ + kp2 * BW + c) * 4);
            cp16(sm_bsh + off, Bh + (size_t)(kp0 + kp2) * N + n0 + c);
            cp16(sm_bsl + off, Bl + (size_t)(kp0 + kp2) * N + n0 + c);
        }
        CP_COMMIT();
    };
    auto storeA = [&](int b) {
        uint32_t* Ash = AshB + b * ASZ;
        uint32_t* Asl = AslB + b * ASZ;
        #pragma unroll
        for (int i = 0; i < A_IT; i++) {
            int flat = tid + i * THREADS;
            int r = flat / (BK / 4), c = (flat % (BK / 4)) * 4;
            uint32_t h0, l0, h1, l1;
            split2(aPF[i].x, aPF[i].y, h0, l0);
            split2(aPF[i].z, aPF[i].w, h1, l1);
            Ash[r * AW + c / 2] = h0; Ash[r * AW + c / 2 + 1] = h1;
            Asl[r * AW + c / 2] = l0; Asl[r * AW + c / 2 + 1] = l1;
        }
    };

    loadA(0);
    cpB(0, 0);
    storeA(0);
    CP_WAIT0();
    __syncthreads();

    for (int k0 = 0; k0 < K; k0 += BK) {
        const int b = (k0 / BK) & 1;
        const bool more = (k0 + BK < K);
        if (more) { loadA(k0 + BK); cpB(k0 + BK, b ^ 1); }

        const uint32_t ash_b = sm_base + (uint32_t)((b * ASZ) * 4);
        const uint32_t asl_b = sm_base + (uint32_t)((2 * ASZ + b * ASZ) * 4);
        const uint32_t* Bsh = BshB + b * BSZ;
        const uint32_t* Bsl = BslB + b * BSZ;

        #pragma unroll
        for (int kk = 0; kk < 2; kk++) {
            const int wof = kk * 8;
            uint32_t Ah[MT][4], Al[MT][4], Bfh[NT][2], Bfl[NT][2];
            #pragma unroll
            for (int i = 0; i < MT; i++) {
                int mr = wm * WM + i * 16;
                uint32_t aoff = (uint32_t)(((mr + 8 * (lt & 1) + lr) * AW
                                           + wof + 4 * (lt >> 1)) * 4);
                ldsm4(Ah[i][0], Ah[i][1], Ah[i][2], Ah[i][3], ash_b + aoff);
                ldsm4(Al[i][0], Al[i][1], Al[i][2], Al[i][3], asl_b + aoff);
            }
            #pragma unroll
            for (int j = 0; j < NT; j++) {
                int nc = wn * WN + j * 8 + g;
                Bfh[j][0] = Bsh[(wof + q) * BW + nc];
                Bfh[j][1] = Bsh[(wof + q + 4) * BW + nc];
                Bfl[j][0] = Bsl[(wof + q) * BW + nc];
                Bfl[j][1] = Bsl[(wof + q + 4) * BW + nc];
            }
            #pragma unroll
            for (int i = 0; i < MT; i++)
                #pragma unroll
                for (int j = 0; j < NT; j++)
                    mma_bf16(acc[i][j], Ah[i], Bfh[j][0], Bfh[j][1]);
            #pragma unroll
            for (int i = 0; i < MT; i++)
                #pragma unroll
                for (int j = 0; j < NT; j++)
                    mma_bf16(acc[i][j], Ah[i], Bfl[j][0], Bfl[j][1]);
            #pragma unroll
            for (int i = 0; i < MT; i++)
                #pragma unroll
                for (int j = 0; j < NT; j++)
                    mma_bf16(acc[i][j], Al[i], Bfh[j][0], Bfh[j][1]);
        }

        if (more) storeA(b ^ 1);
        CP_WAIT0();
        __syncthreads();
    }

    const unsigned FULL = 0xffffffffu;
    #pragma unroll
    for (int i = 0; i < MT; i++) {
        int row0 = m0 + wm * WM + i * 16 + g;
        #pragma unroll
        for (int j = 0; j < NT; j++) {
            int col = n0 + wn * WN + j * 8 + 2 * q;
            float bx = bias[col], by = bias[col + 1];
            float v0 = acc[i][j][0] + bx, v1 = acc[i][j][1] + by;
            float v2 = acc[i][j][2] + bx, v3 = acc[i][j][3] + by;
            if constexpr (CMODE == 0) {
                float2 w0 = { v0, v1 }, w1 = { v2, v3 };
                *(float2*)(C + (size_t)row0 * N + col) = w0;
                *(float2*)(C + (size_t)(row0 + 8) * N + col) = w1;
            } else if constexpr (CMODE == 4) {
                v0 *= LOG2E; v1 *= LOG2E; v2 *= LOG2E; v3 *= LOG2E;
                uint32_t h, l;
                splitf16(v0, v1, h, l);
                Ch[(size_t)row0 * (N / 2) + col / 2] = h;
                Cl[(size_t)row0 * (N / 2) + col / 2] = l;
                splitf16(v2, v3, h, l);
                Ch[(size_t)(row0 + 8) * (N / 2) + col / 2] = h;
                Cl[(size_t)(row0 + 8) * (N / 2) + col / 2] = l;
            } else {
                if (!isV) {
                    Ch[(size_t)row0 * (N / 2) + col / 2] = packf16(v0, v1);
                    Ch[(size_t)(row0 + 8) * (N / 2) + col / 2] = packf16(v2, v3);
                } else {
                    float p0 = __shfl_xor_sync(FULL, v0, 4);
                    float p1 = __shfl_xor_sync(FULL, v1, 4);
                    float p2 = __shfl_xor_sync(FULL, v2, 4);
                    float p3 = __shfl_xor_sync(FULL, v3, 4);
                    uint32_t h, l;
                    if ((g & 1) == 0) {
                        split2(v0, p0, h, l);
                        Ch[(size_t)col * (S_LEN / 2) + row0 / 2] = h;
                        Cl[(size_t)col * (S_LEN / 2) + row0 / 2] = l;
                        split2(v2, p2, h, l);
                        Ch[(size_t)col * (S_LEN / 2) + (row0 + 8) / 2] = h;
                        Cl[(size_t)col * (S_LEN / 2) + (row0 + 8) / 2] = l;
                    } else {
                        split2(p1, v1, h, l);
                        Ch[(size_t)(col + 1) * (S_LEN / 2) + (row0 - 1) / 2] = h;
                        Cl[(size_t)(col + 1) * (S_LEN / 2) + (row0 - 1) / 2] = l;
                        split2(p3, v3, h, l);
                        Ch[(size_t)(col + 1) * (S_LEN / 2) + (row0 + 7) / 2] = h;
                        Cl[(size_t)(col + 1) * (S_LEN / 2) + (row0 + 7) / 2] = l;
                    }
                }
            }
        }
    }
}

// ---------------- flash MQA attention (fp16 2-pass S, bf16x3 PV) ------------
// Exact R11 version (best measured: 465 us, tensor 60.7%).
// smem: 2 buffers x [K 9216 | VH 9216 | VL 9216]; Q (fp16 h/l) above.
#define PW   36
#define BUFB 27648
#define QH_OFF 55296
#define QL_OFF 73728
#define ATTN_SMEM 92160

__global__ __launch_bounds__(256, 2)
void mqa_attn_c(const uint32_t* __restrict__ qph, const uint32_t* __restrict__ qpl,
                const uint32_t* __restrict__ kp,
                const uint32_t* __restrict__ vth, const uint32_t* __restrict__ vtl,
                float* __restrict__ out)
{
    extern __shared__ char smraw[];
    const uint32_t smb = smem_u32(smraw);
    const int tid  = threadIdx.x;
    const int warp = tid >> 5, lane = tid & 31;
    const int gl = lane >> 2, q = lane & 3;
    const int lt = lane >> 3, lr = lane & 7;
    const int head = blockIdx.y;
    const int q0 = blockIdx.x * 128;
    const unsigned FULL = 0xffffffffu;

    // ---- stage packed Q (fp16, pre-scaled by log2e) ----
    #pragma unroll
    for (int i = 0; i < 4; i++) {
        int idx = tid + i * 256;
        int r = idx >> 3, c4 = (idx & 7) * 4;
        *(uint4*)(smraw + QH_OFF + (r * PW + c4) * 4) =
            *(const uint4*)(qph + (size_t)(q0 + r) * 512 + head * 32 + c4);
        *(uint4*)(smraw + QL_OFF + (r * PW + c4) * 4) =
            *(const uint4*)(qpl + (size_t)(q0 + r) * 512 + head * 32 + c4);
    }

    // ---- async K/V chunk load ----
    const int kkey = tid >> 2, kw0 = (tid & 3) * 8;
    auto loadKV = [&](int k0, int bb) {
        uint32_t base = smb + (uint32_t)bb + (kkey * PW + kw0) * 4;
        const uint32_t* ph = kp + (size_t)(k0 + kkey) * 32 + kw0;
        cp16(base,      ph);
        cp16(base + 16, ph + 4);
        const uint32_t* vh = vth + (size_t)kkey * (S_LEN / 2) + (k0 >> 1) + kw0;
        const uint32_t* vl = vtl + (size_t)kkey * (S_LEN / 2) + (k0 >> 1) + kw0;
        cp16(base + 9216,       vh);
        cp16(base + 9216 + 16,  vh + 4);
        cp16(base + 18432,      vl);
        cp16(base + 18432 + 16, vl + 4);
        CP_COMMIT();
    };

    loadKV(0, 0);
    __syncthreads();   // Q stores visible

    // ---- Q fragments via ldmatrix ----
    uint32_t Qh[4][4], Ql[4][4];
    {
        uint32_t brow = (uint32_t)(warp * 16 + 8 * (lt & 1) + lr);
        #pragma unroll
        for (int s = 0; s < 4; s++) {
            uint32_t aoff = (brow * PW + 8 * s + 4 * (lt >> 1)) * 4;
            ldsm4(Qh[s][0], Qh[s][1], Qh[s][2], Qh[s][3], smb + QH_OFF + aoff);
            ldsm4(Ql[s][0], Ql[s][1], Ql[s][2], Ql[s][3], smb + QL_OFF + aoff);
        }
    }
    CP_WAIT0();
    __syncthreads();

    float O[8][4];
    #pragma unroll
    for (int j = 0; j < 8; j++)
        #pragma unroll
        for (int e = 0; e < 4; e++) O[j][e] = 0.f;
    float ls0 = 0.f, ls1 = 0.f;

    float Sfc[2][2][4];

    auto issueS = [&](int bb, int g, int slot) {
        uint32_t kf[2][8];
        uint32_t krow = (uint32_t)(16 * g + 8 * (lt >> 1) + lr);
        #pragma unroll
        for (int s = 0; s < 4; s++) {
            uint32_t aoff = (krow * PW + 8 * s + 4 * (lt & 1)) * 4;
            ldsm4(kf[0][2*s], kf[0][2*s+1], kf[1][2*s], kf[1][2*s+1],
                  smb + bb + aoff);
        }
        #pragma unroll
        for (int jj = 0; jj < 2; jj++)
            #pragma unroll
            for (int e = 0; e < 4; e++) Sfc[slot][jj][e] = 0.f;
        #pragma unroll
        for (int s = 0; s < 4; s++)
            #pragma unroll
            for (int jj = 0; jj < 2; jj++)
                mma_f16(Sfc[slot][jj], Qh[s], kf[jj][2 * s], kf[jj][2 * s + 1]);
        #pragma unroll
        for (int s = 0; s < 4; s++)
            #pragma unroll
            for (int jj = 0; jj < 2; jj++)
                mma_f16(Sfc[slot][jj], Ql[s], kf[jj][2 * s], kf[jj][2 * s + 1]);
    };

    auto epiPV = [&](int bb, int g, int slot) {
        float ev[2][4];
        #pragma unroll
        for (int jj = 0; jj < 2; jj++)
            #pragma unroll
            for (int e = 0; e < 4; e++)
                ev[jj][e] = ex2f(Sfc[slot][jj][e]);
        #pragma unroll
        for (int jj = 0; jj < 2; jj++) {
            ls0 += ev[jj][0] + ev[jj][1];
            ls1 += ev[jj][2] + ev[jj][3];
        }
        uint32_t Ph[4], Pl[4];
        split2(ev[0][0], ev[0][1], Ph[0], Pl[0]);
        split2(ev[0][2], ev[0][3], Ph[1], Pl[1]);
        split2(ev[1][0], ev[1][1], Ph[2], Pl[2]);
        split2(ev[1][2], ev[1][3], Ph[3], Pl[3]);
        uint32_t vh[16], vl[16];
        #pragma unroll
        for (int c = 0; c < 4; c++) {
            uint32_t vrow = (uint32_t)(8 * (2 * c + (lt >> 1)) + lr);
            uint32_t aoff = (vrow * PW + 8 * g + 4 * (lt & 1)) * 4;
            ldsm4(vh[4*c], vh[4*c+1], vh[4*c+2], vh[4*c+3],
                  smb + bb + 9216 + aoff);
            ldsm4(vl[4*c], vl[4*c+1], vl[4*c+2], vl[4*c+3],
                  smb + bb + 18432 + aoff);
        }
        #pragma unroll
        for (int jv = 0; jv < 8; jv++) mma_bf16(O[jv], Ph, vh[2 * jv], vh[2 * jv + 1]);
        #pragma unroll
        for (int jv = 0; jv < 8; jv++) mma_bf16(O[jv], Ph, vl[2 * jv], vl[2 * jv + 1]);
        #pragma unroll
        for (int jv = 0; jv < 8; jv++) mma_bf16(O[jv], Pl, vh[2 * jv], vh[2 * jv + 1]);
    };

    for (int ci = 0; ci < S_LEN / 64; ci++) {
        const int bb = (ci & 1) * BUFB;
        if (ci < S_LEN / 64 - 1) loadKV((ci + 1) * 64, bb ^ BUFB);
        issueS(bb, 0, 0);
        #pragma unroll
        for (int g = 0; g < 4; g++) {
            if (g < 3) issueS(bb, g + 1, (g + 1) & 1);
            epiPV(bb, g, g & 1);
        }
        CP_WAIT0();
        __syncthreads();
    }

    // final row-sum reduction and write
    ls0 += __shfl_xor_sync(FULL, ls0, 1);
    ls0 += __shfl_xor_sync(FULL, ls0, 2);
    ls1 += __shfl_xor_sync(FULL, ls1, 1);
    ls1 += __shfl_xor_sync(FULL, ls1, 2);
    float inv0 = 1.f / ls0, inv1 = 1.f / ls1;
    int row0 = q0 + warp * 16 + gl;
    #pragma unroll
    for (int j = 0; j < 8; j++) {
        int col = head * DKV + j * 8 + 2 * q;
        float2 w0 = { O[j][0] * inv0, O[j][1] * inv0 };
        float2 w1 = { O[j][2] * inv1, O[j][3] * inv1 };
        *(float2*)(out + (size_t)row0 * DMODEL + col) = w0;
        *(float2*)(out + (size_t)(row0 + 8) * DMODEL + col) = w1;
    }
}

// ---------------- launch ----------------------------------------------------
extern "C" void kernel_launch(void* const* d_in, const int* in_sizes, int n_in,
                              void* d_out, int out_size)
{
    const float* q  = (const float*)d_in[0];
    const float* k  = (const float*)d_in[1];
    const float* v  = (const float*)d_in[2];
    const float* Wq = (const float*)d_in[3];
    const float* bq = (const float*)d_in[4];
    const float* Wk = (const float*)d_in[5];
    const float* bk = (const float*)d_in[6];
    const float* Wv = (const float*)d_in[7];
    const float* bv = (const float*)d_in[8];
    const float* Wo = (const float*)d_in[9];
    const float* bo = (const float*)d_in[10];
    float* out = (float*)d_out;

    void* p;
    cudaGetSymbolAddress(&p, g_att);  float* att = (float*)p;
    cudaGetSymbolAddress(&p, g_wqh);  uint32_t* wqh = (uint32_t*)p;
    cudaGetSymbolAddress(&p, g_wql);  uint32_t* wql = (uint32_t*)p;
    cudaGetSymbolAddress(&p, g_wkh);  uint32_t* wkh = (uint32_t*)p;
    cudaGetSymbolAddress(&p, g_wkl);  uint32_t* wkl = (uint32_t*)p;
    cudaGetSymbolAddress(&p, g_wvh);  uint32_t* wvh = (uint32_t*)p;
    cudaGetSymbolAddress(&p, g_wvl);  uint32_t* wvl = (uint32_t*)p;
    cudaGetSymbolAddress(&p, g_woh);  uint32_t* woh = (uint32_t*)p;
    cudaGetSymbolAddress(&p, g_wol);  uint32_t* wol = (uint32_t*)p;
    cudaGetSymbolAddress(&p, g_qph);  uint32_t* qph = (uint32_t*)p;
    cudaGetSymbolAddress(&p, g_qpl);  uint32_t* qpl = (uint32_t*)p;
    cudaGetSymbolAddress(&p, g_kp);   uint32_t* kpp = (uint32_t*)p;
    cudaGetSymbolAddress(&p, g_vth);  uint32_t* vth = (uint32_t*)p;
    cudaGetSymbolAddress(&p, g_vtl);  uint32_t* vtl = (uint32_t*)p;

    constexpr int SM_BIG   = (4 * 128 * 20 + 4 * 16 * 136) * 4;  // 75776
    constexpr int SM_SMALL = (4 * 64 * 20 + 4 * 16 * 72) * 4;    // 38912

    cudaFuncSetAttribute((const void*)(bgemm3<128, 128, 32, 2, 4, 4>),
                         cudaFuncAttributeMaxDynamicSharedMemorySize, SM_BIG);
    cudaFuncSetAttribute((const void*)(bgemm3<128, 128, 32, 2, 4, 0>),
                         cudaFuncAttributeMaxDynamicSharedMemorySize, SM_BIG);
    cudaFuncSetAttribute((const void*)(bgemm3<64, 64, 32, 2, 4, 3>),
                         cudaFuncAttributeMaxDynamicSharedMemorySize, SM_SMALL);
    cudaFuncSetAttribute((const void*)mqa_attn_c,
                         cudaFuncAttributeMaxDynamicSharedMemorySize, ATTN_SMEM);

    // weight pre-split
    splitAll<<<(2 * 512 * 1024 + 2 * 512 * 64 + 255) / 256, 256>>>(
        Wq, Wo, Wk, Wv, wqh, wql, woh, wol, wkh, wkl, wvh, wvl);

    // Q projection (fp16 h/l, log2e-scaled epilogue)
    bgemm3<128, 128, 32, 2, 4, 4>
        <<<dim3(DMODEL / 128, S_LEN / 128), 256, SM_BIG>>>(
            q, wqh, wql, bq, nullptr, qph, qpl,
            nullptr, nullptr, nullptr, nullptr, nullptr, nullptr,
            S_LEN, DMODEL, DMODEL);
    // K + V projections fused
    bgemm3<64, 64, 32, 2, 4, 3>
        <<<dim3(2, S_LEN / 64), 256, SM_SMALL>>>(
            k, wkh, wkl, bk, nullptr, kpp, nullptr,
            v, wvh, wvl, bv, vth, vtl,
            S_LEN, DKV, DMODEL);
    // attention (R11 version)
    mqa_attn_c<<<dim3(S_LEN / 128, HEADS), 256, ATTN_SMEM>>>(qph, qpl, kpp,
                                                             vth, vtl, att);
    // O projection
    bgemm3<128, 128, 32, 2, 4, 0>
        <<<dim3(DMODEL / 128, S_LEN / 128), 256, SM_BIG>>>(
            att, woh, wol, bo, out, nullptr, nullptr,
            nullptr, nullptr, nullptr, nullptr, nullptr, nullptr,
            S_LEN, DMODEL, DMODEL);
}

// round 14
// speedup vs baseline: 1.0419x; 1.0088x over previous
#include <cuda_runtime.h>
#include <cstdint>

#define S_LEN   4096
#define DMODEL  1024
#define HEADS   16
#define DKV     64
#define LOG2E   1.4426950408889634f

// ---------------- scratch ---------------------------------------------------
__device__ uint32_t g_wqh[512 * 1024], g_wql[512 * 1024];
__device__ uint32_t g_wkh[512 * 64],   g_wkl[512 * 64];
__device__ uint32_t g_wvh[512 * 64],   g_wvl[512 * 64];
__device__ uint32_t g_woh[512 * 1024], g_wol[512 * 1024];
__device__ uint32_t g_qph[S_LEN * 512], g_qpl[S_LEN * 512];   // fp16 pairs (scaled by log2e)
__device__ uint32_t g_kp[S_LEN * 32];                          // fp16 pairs [key][dk-pair]
__device__ uint32_t g_vth[64 * (S_LEN / 2)], g_vtl[64 * (S_LEN / 2)]; // bf16 [dk][key-pair]
__device__ uint32_t g_oh[S_LEN * 512], g_ol[S_LEN * 512];      // attn out, bf16 h/l pairs

// ---------------- numeric helpers -------------------------------------------
__device__ __forceinline__ void split2(float x, float y, uint32_t& h, uint32_t& l) {
    uint32_t hp;
    asm("cvt.rn.bf16x2.f32 %0,%1,%2;" : "=r"(hp) : "f"(y), "f"(x));
    float hx = __uint_as_float(hp << 16);
    float hy = __uint_as_float(hp & 0xffff0000u);
    asm("cvt.rn.bf16x2.f32 %0,%1,%2;" : "=r"(l) : "f"(y - hy), "f"(x - hx));
    h = hp;
}
__device__ __forceinline__ void splitf16(float x, float y, uint32_t& h, uint32_t& l) {
    uint32_t hp;
    asm("cvt.rn.f16x2.f32 %0,%1,%2;" : "=r"(hp) : "f"(y), "f"(x));
    float hx, hy;
    asm("{.reg .f16 a,b; mov.b32 {a,b},%2; cvt.f32.f16 %0,a; cvt.f32.f16 %1,b;}"
        : "=f"(hx), "=f"(hy) : "r"(hp));
    asm("cvt.rn.f16x2.f32 %0,%1,%2;" : "=r"(l) : "f"(y - hy), "f"(x - hx));
    h = hp;
}
__device__ __forceinline__ uint32_t packf16(float x, float y) {
    uint32_t r;
    asm("cvt.rn.f16x2.f32 %0,%1,%2;" : "=r"(r) : "f"(y), "f"(x));
    return r;
}
__device__ __forceinline__ float ex2f(float x) {
    float r;
    asm("ex2.approx.f32 %0,%1;" : "=f"(r) : "f"(x));
    return r;
}
__device__ __forceinline__ void mma_bf16(float* d, const uint32_t* a,
                                         uint32_t b0, uint32_t b1) {
    asm volatile("mma.sync.aligned.m16n8k16.row.col.f32.bf16.bf16.f32 "
        "{%0,%1,%2,%3},{%4,%5,%6,%7},{%8,%9},{%0,%1,%2,%3};"
        : "+f"(d[0]), "+f"(d[1]), "+f"(d[2]), "+f"(d[3])
        : "r"(a[0]), "r"(a[1]), "r"(a[2]), "r"(a[3]), "r"(b0), "r"(b1));
}
__device__ __forceinline__ void mma_f16(float* d, const uint32_t* a,
                                        uint32_t b0, uint32_t b1) {
    asm volatile("mma.sync.aligned.m16n8k16.row.col.f32.f16.f16.f32 "
        "{%0,%1,%2,%3},{%4,%5,%6,%7},{%8,%9},{%0,%1,%2,%3};"
        : "+f"(d[0]), "+f"(d[1]), "+f"(d[2]), "+f"(d[3])
        : "r"(a[0]), "r"(a[1]), "r"(a[2]), "r"(a[3]), "r"(b0), "r"(b1));
}
__device__ __forceinline__ void ldsm4(uint32_t& r0, uint32_t& r1,
                                      uint32_t& r2, uint32_t& r3, uint32_t addr) {
    asm volatile("ldmatrix.sync.aligned.m8n8.x4.shared.b16 {%0,%1,%2,%3}, [%4];"
                 : "=r"(r0), "=r"(r1), "=r"(r2), "=r"(r3) : "r"(addr));
}
__device__ __forceinline__ uint32_t smem_u32(const void* p) {
    uint32_t a;
    asm("{ .reg .u64 t; cvta.to.shared.u64 t, %1; cvt.u32.u64 %0, t; }"
        : "=r"(a) : "l"(p));
    return a;
}
__device__ __forceinline__ void cp16(uint32_t saddr, const void* g) {
    asm volatile("cp.async.cg.shared.global [%0], [%1], 16;" :: "r"(saddr), "l"(g));
}
#define CP_COMMIT() asm volatile("cp.async.commit_group;" ::: "memory")
#define CP_WAIT0()  asm volatile("cp.async.wait_group 0;"  ::: "memory")

// ---------------- combined weight pre-split (bf16 h/l for GEMM B) -----------
__global__ __launch_bounds__(256)
void splitAll(const float* __restrict__ Wq, const float* __restrict__ Wo,
              const float* __restrict__ Wk, const float* __restrict__ Wv,
              uint32_t* __restrict__ wqh, uint32_t* __restrict__ wql,
              uint32_t* __restrict__ woh, uint32_t* __restrict__ wol,
              uint32_t* __restrict__ wkh, uint32_t* __restrict__ wkl,
              uint32_t* __restrict__ wvh, uint32_t* __restrict__ wvl)
{
    constexpr int BIG = 512 * 1024, SMALL = 512 * 64;
    int idx = blockIdx.x * 256 + threadIdx.x;
    const float* W; uint32_t *Wh, *Wl; int i, N;
    if (idx < BIG)               { W = Wq; Wh = wqh; Wl = wql; i = idx;            N = 1024; }
    else if (idx < 2 * BIG)      { W = Wo; Wh = woh; Wl = wol; i = idx - BIG;      N = 1024; }
    else if (idx < 2 * BIG + SMALL) { W = Wk; Wh = wkh; Wl = wkl; i = idx - 2*BIG; N = 64; }
    else if (idx < 2 * BIG + 2 * SMALL) { W = Wv; Wh = wvh; Wl = wvl; i = idx - 2*BIG - SMALL; N = 64; }
    else return;
    int kp = i / N, n = i - kp * N;
    float a = W[(size_t)(2 * kp) * N + n];
    float b = W[(size_t)(2 * kp + 1) * N + n];
    uint32_t h, l;
    split2(a, b, h, l);
    Wh[i] = h; Wl[i] = l;
}

// ---------------- bf16x3 GEMM, cp.async double-buffered, LDSM A -------------
// CMODE 0: fp32 A (split in-kernel), fp32 C.
// CMODE 3: fused K/V proj — blockIdx.x 0: K fp16-pair epilogue; 1: V-transposed.
// CMODE 4: fp32 A, Q-proj epilogue (LOG2E scale, fp16 h/l pairs).
// CMODE 5: PRE-SPLIT A (uint32 h/l arrays via Bh2/Bl2 params, cp.async), fp32 C.
template<int BM, int BN, int BK, int WARPS_M, int WARPS_N, int CMODE>
__global__ __launch_bounds__(WARPS_M * WARPS_N * 32)
void bgemm3(const float* __restrict__ A, const uint32_t* __restrict__ Bh,
            const uint32_t* __restrict__ Bl, const float* __restrict__ bias,
            float* __restrict__ C, uint32_t* __restrict__ Ch,
            uint32_t* __restrict__ Cl,
            const float* __restrict__ A2, const uint32_t* __restrict__ Bh2,
            const uint32_t* __restrict__ Bl2, const float* __restrict__ bias2,
            uint32_t* __restrict__ Ch2, uint32_t* __restrict__ Cl2,
            int M, int N, int K)
{
    constexpr int THREADS = WARPS_M * WARPS_N * 32;
    constexpr int WM = BM / WARPS_M, WN = BN / WARPS_N;
    constexpr int MT = WM / 16, NT = WN / 8;
    constexpr int KW = BK / 2;
    constexpr int AW = KW + 4;       // 20 words: ldsm rows conflict-free
    constexpr int BW = BN + 8;
    constexpr int ASZ = BM * AW;
    constexpr int BSZ = KW * BW;
    constexpr int A_IT = BM * BK / (4 * THREADS);
    constexpr int B_IT = KW * (BN / 4) / THREADS;
    constexpr bool PRE_A = (CMODE == 5);

    extern __shared__ uint32_t smw[];
    uint32_t* AshB = smw;
    uint32_t* AslB = smw + 2 * ASZ;
    uint32_t* BshB = smw + 4 * ASZ;
    uint32_t* BslB = smw + 4 * ASZ + 2 * BSZ;
    const uint32_t sm_base = smem_u32(smw);
    const uint32_t sm_ash = sm_base;
    const uint32_t sm_asl = sm_base + (uint32_t)(2 * ASZ * 4);
    const uint32_t sm_bsh = smem_u32(BshB);
    const uint32_t sm_bsl = smem_u32(BslB);

    bool isV = false;
    if constexpr (CMODE == 3) {
        if (blockIdx.x == 1) {
            isV = true;
            A = A2; Bh = Bh2; Bl = Bl2; bias = bias2; Ch = Ch2; Cl = Cl2;
        }
    }

    const int tid  = threadIdx.x;
    const int warp = tid >> 5, lane = tid & 31;
    const int g = lane >> 2, q = lane & 3;
    const int lt = lane >> 3, lr = lane & 7;
    const int wm = warp / WARPS_N, wn = warp % WARPS_N;
    const int m0 = blockIdx.y * BM;
    const int n0 = (CMODE == 3) ? 0 : blockIdx.x * BN;

    float acc[MT][NT][4];
    #pragma unroll
    for (int i = 0; i < MT; i++)
        #pragma unroll
        for (int j = 0; j < NT; j++)
            #pragma unroll
            for (int e = 0; e < 4; e++) acc[i][j][e] = 0.f;

    float4 aPF[PRE_A ? 1 : A_IT];

    auto loadA = [&](int k0) {
        if constexpr (!PRE_A) {
            #pragma unroll
            for (int i = 0; i < A_IT; i++) {
                int flat = tid + i * THREADS;
                int r = flat / (BK / 4), c = (flat % (BK / 4)) * 4;
                aPF[i] = *(const float4*)(A + (size_t)(m0 + r) * K + k0 + c);
            }
        }
    };
    // CMODE 5: A pre-split h/l arrays in Bh2/Bl2; cp.async straight to smem
    auto cpA = [&](int k0, int b) {
        if constexpr (PRE_A) {
            int kp0 = k0 / 2;
            #pragma unroll
            for (int i = 0; i < BM * KW / (4 * THREADS); i++) {
                int flat = tid + i * THREADS;
                int r = flat / (KW / 4), c = (flat % (KW / 4)) * 4;
                uint32_t off = (uint32_t)((b * ASZ + r * AW + c) * 4);
                cp16(sm_ash + off, Bh2 + (size_t)(m0 + r) * (K / 2) + kp0 + c);
                cp16(sm_asl + off, Bl2 + (size_t)(m0 + r) * (K / 2) + kp0 + c);
            }
        }
    };
    auto cpB = [&](int k0, int b) {
        int kp0 = k0 / 2;
        #pragma unroll
        for (int i = 0; i < B_IT; i++) {
            int flat = tid + i * THREADS;
            int kp2 = flat / (BN / 4), c = (flat % (BN / 4)) * 4;
            uint32_t off = (uint32_t)((b * BSZ + kp2 * BW + c) * 4);
            cp16(sm_bsh + off, Bh + (size_t)(kp0 + kp2) * N + n0 + c);
            cp16(sm_bsl + off, Bl + (size_t)(kp0 + kp2) * N + n0 + c);
        }
        CP_COMMIT();
    };
    auto storeA = [&](int b) {
        if constexpr (!PRE_A) {
            uint32_t* Ash = AshB + b * ASZ;
            uint32_t* Asl = AslB + b * ASZ;
            #pragma unroll
            for (int i = 0; i < A_IT; i++) {
                int flat = tid + i * THREADS;
                int r = flat / (BK / 4), c = (flat % (BK / 4)) * 4;
                uint32_t h0, l0, h1, l1;
                split2(aPF[i].x, aPF[i].y, h0, l0);
                split2(aPF[i].z, aPF[i].w, h1, l1);
                Ash[r * AW + c / 2] = h0; Ash[r * AW + c / 2 + 1] = h1;
                Asl[r * AW + c / 2] = l0; Asl[r * AW + c / 2 + 1] = l1;
            }
        }
    };

    loadA(0);
    cpA(0, 0);
    cpB(0, 0);
    storeA(0);
    CP_WAIT0();
    __syncthreads();

    for (int k0 = 0; k0 < K; k0 += BK) {
        const int b = (k0 / BK) & 1;
        const bool more = (k0 + BK < K);
        if (more) { loadA(k0 + BK); cpA(k0 + BK, b ^ 1); cpB(k0 + BK, b ^ 1); }

        const uint32_t ash_b = sm_ash + (uint32_t)((b * ASZ) * 4);
        const uint32_t asl_b = sm_asl + (uint32_t)((b * ASZ) * 4);
        const uint32_t* Bsh = BshB + b * BSZ;
        const uint32_t* Bsl = BslB + b * BSZ;

        #pragma unroll
        for (int kk = 0; kk < 2; kk++) {
            const int wof = kk * 8;
            uint32_t Ah[MT][4], Al[MT][4], Bfh[NT][2], Bfl[NT][2];
            #pragma unroll
            for (int i = 0; i < MT; i++) {
                int mr = wm * WM + i * 16;
                uint32_t aoff = (uint32_t)(((mr + 8 * (lt & 1) + lr) * AW
                                           + wof + 4 * (lt >> 1)) * 4);
                ldsm4(Ah[i][0], Ah[i][1], Ah[i][2], Ah[i][3], ash_b + aoff);
                ldsm4(Al[i][0], Al[i][1], Al[i][2], Al[i][3], asl_b + aoff);
            }
            #pragma unroll
            for (int j = 0; j < NT; j++) {
                int nc = wn * WN + j * 8 + g;
                Bfh[j][0] = Bsh[(wof + q) * BW + nc];
                Bfh[j][1] = Bsh[(wof + q + 4) * BW + nc];
                Bfl[j][0] = Bsl[(wof + q) * BW + nc];
                Bfl[j][1] = Bsl[(wof + q + 4) * BW + nc];
            }
            #pragma unroll
            for (int i = 0; i < MT; i++)
                #pragma unroll
                for (int j = 0; j < NT; j++)
                    mma_bf16(acc[i][j], Ah[i], Bfh[j][0], Bfh[j][1]);
            #pragma unroll
            for (int i = 0; i < MT; i++)
                #pragma unroll
                for (int j = 0; j < NT; j++)
                    mma_bf16(acc[i][j], Ah[i], Bfl[j][0], Bfl[j][1]);
            #pragma unroll
            for (int i = 0; i < MT; i++)
                #pragma unroll
                for (int j = 0; j < NT; j++)
                    mma_bf16(acc[i][j], Al[i], Bfh[j][0], Bfh[j][1]);
        }

        if (more) storeA(b ^ 1);
        CP_WAIT0();
        __syncthreads();
    }

    const unsigned FULL = 0xffffffffu;
    #pragma unroll
    for (int i = 0; i < MT; i++) {
        int row0 = m0 + wm * WM + i * 16 + g;
        #pragma unroll
        for (int j = 0; j < NT; j++) {
            int col = n0 + wn * WN + j * 8 + 2 * q;
            float bx = bias[col], by = bias[col + 1];
            float v0 = acc[i][j][0] + bx, v1 = acc[i][j][1] + by;
            float v2 = acc[i][j][2] + bx, v3 = acc[i][j][3] + by;
            if constexpr (CMODE == 0 || CMODE == 5) {
                float2 w0 = { v0, v1 }, w1 = { v2, v3 };
                *(float2*)(C + (size_t)row0 * N + col) = w0;
                *(float2*)(C + (size_t)(row0 + 8) * N + col) = w1;
            } else if constexpr (CMODE == 4) {
                v0 *= LOG2E; v1 *= LOG2E; v2 *= LOG2E; v3 *= LOG2E;
                uint32_t h, l;
                splitf16(v0, v1, h, l);
                Ch[(size_t)row0 * (N / 2) + col / 2] = h;
                Cl[(size_t)row0 * (N / 2) + col / 2] = l;
                splitf16(v2, v3, h, l);
                Ch[(size_t)(row0 + 8) * (N / 2) + col / 2] = h;
                Cl[(size_t)(row0 + 8) * (N / 2) + col / 2] = l;
            } else {
                if (!isV) {
                    Ch[(size_t)row0 * (N / 2) + col / 2] = packf16(v0, v1);
                    Ch[(size_t)(row0 + 8) * (N / 2) + col / 2] = packf16(v2, v3);
                } else {
                    float p0 = __shfl_xor_sync(FULL, v0, 4);
                    float p1 = __shfl_xor_sync(FULL, v1, 4);
                    float p2 = __shfl_xor_sync(FULL, v2, 4);
                    float p3 = __shfl_xor_sync(FULL, v3, 4);
                    uint32_t h, l;
                    if ((g & 1) == 0) {
                        split2(v0, p0, h, l);
                        Ch[(size_t)col * (S_LEN / 2) + row0 / 2] = h;
                        Cl[(size_t)col * (S_LEN / 2) + row0 / 2] = l;
                        split2(v2, p2, h, l);
                        Ch[(size_t)col * (S_LEN / 2) + (row0 + 8) / 2] = h;
                        Cl[(size_t)col * (S_LEN / 2) + (row0 + 8) / 2] = l;
                    } else {
                        split2(p1, v1, h, l);
                        Ch[(size_t)(col + 1) * (S_LEN / 2) + (row0 - 1) / 2] = h;
                        Cl[(size_t)(col + 1) * (S_LEN / 2) + (row0 - 1) / 2] = l;
                        split2(p3, v3, h, l);
                        Ch[(size_t)(col + 1) * (S_LEN / 2) + (row0 + 7) / 2] = h;
                        Cl[(size_t)(col + 1) * (S_LEN / 2) + (row0 + 7) / 2] = l;
                    }
                }
            }
        }
    }
}

// ---------------- flash MQA attention (fp16 2-pass S, bf16x3 PV) ------------
// R11 core; epilogue emits packed bf16 h/l pairs (O-proj A layout).
#define PW   36
#define BUFB 27648
#define QH_OFF 55296
#define QL_OFF 73728
#define ATTN_SMEM 92160

__global__ __launch_bounds__(256, 2)
void mqa_attn_c(const uint32_t* __restrict__ qph, const uint32_t* __restrict__ qpl,
                const uint32_t* __restrict__ kp,
                const uint32_t* __restrict__ vth, const uint32_t* __restrict__ vtl,
                uint32_t* __restrict__ oh, uint32_t* __restrict__ ol)
{
    extern __shared__ char smraw[];
    const uint32_t smb = smem_u32(smraw);
    const int tid  = threadIdx.x;
    const int warp = tid >> 5, lane = tid & 31;
    const int gl = lane >> 2, q = lane & 3;
    const int lt = lane >> 3, lr = lane & 7;
    const int head = blockIdx.y;
    const int q0 = blockIdx.x * 128;
    const unsigned FULL = 0xffffffffu;

    // ---- stage packed Q (fp16, pre-scaled by log2e) ----
    #pragma unroll
    for (int i = 0; i < 4; i++) {
        int idx = tid + i * 256;
        int r = idx >> 3, c4 = (idx & 7) * 4;
        *(uint4*)(smraw + QH_OFF + (r * PW + c4) * 4) =
            *(const uint4*)(qph + (size_t)(q0 + r) * 512 + head * 32 + c4);
        *(uint4*)(smraw + QL_OFF + (r * PW + c4) * 4) =
            *(const uint4*)(qpl + (size_t)(q0 + r) * 512 + head * 32 + c4);
    }

    // ---- async K/V chunk load ----
    const int kkey = tid >> 2, kw0 = (tid & 3) * 8;
    auto loadKV = [&](int k0, int bb) {
        uint32_t base = smb + (uint32_t)bb + (kkey * PW + kw0) * 4;
        const uint32_t* ph = kp + (size_t)(k0 + kkey) * 32 + kw0;
        cp16(base,      ph);
        cp16(base + 16, ph + 4);
        const uint32_t* vh = vth + (size_t)kkey * (S_LEN / 2) + (k0 >> 1) + kw0;
        const uint32_t* vl = vtl + (size_t)kkey * (S_LEN / 2) + (k0 >> 1) + kw0;
        cp16(base + 9216,       vh);
        cp16(base + 9216 + 16,  vh + 4);
        cp16(base + 18432,      vl);
        cp16(base + 18432 + 16, vl + 4);
        CP_COMMIT();
    };

    loadKV(0, 0);
    __syncthreads();   // Q stores visible

    // ---- Q fragments via ldmatrix ----
    uint32_t Qh[4][4], Ql[4][4];
    {
        uint32_t brow = (uint32_t)(warp * 16 + 8 * (lt & 1) + lr);
        #pragma unroll
        for (int s = 0; s < 4; s++) {
            uint32_t aoff = (brow * PW + 8 * s + 4 * (lt >> 1)) * 4;
            ldsm4(Qh[s][0], Qh[s][1], Qh[s][2], Qh[s][3], smb + QH_OFF + aoff);
            ldsm4(Ql[s][0], Ql[s][1], Ql[s][2], Ql[s][3], smb + QL_OFF + aoff);
        }
    }
    CP_WAIT0();
    __syncthreads();

    float O[8][4];
    #pragma unroll
    for (int j = 0; j < 8; j++)
        #pragma unroll
        for (int e = 0; e < 4; e++) O[j][e] = 0.f;
    float ls0 = 0.f, ls1 = 0.f;

    float Sfc[2][2][4];

    auto issueS = [&](int bb, int g, int slot) {
        uint32_t kf[2][8];
        uint32_t krow = (uint32_t)(16 * g + 8 * (lt >> 1) + lr);
        #pragma unroll
        for (int s = 0; s < 4; s++) {
            uint32_t aoff = (krow * PW + 8 * s + 4 * (lt & 1)) * 4;
            ldsm4(kf[0][2*s], kf[0][2*s+1], kf[1][2*s], kf[1][2*s+1],
                  smb + bb + aoff);
        }
        #pragma unroll
        for (int jj = 0; jj < 2; jj++)
            #pragma unroll
            for (int e = 0; e < 4; e++) Sfc[slot][jj][e] = 0.f;
        #pragma unroll
        for (int s = 0; s < 4; s++)
            #pragma unroll
            for (int jj = 0; jj < 2; jj++)
                mma_f16(Sfc[slot][jj], Qh[s], kf[jj][2 * s], kf[jj][2 * s + 1]);
        #pragma unroll
        for (int s = 0; s < 4; s++)
            #pragma unroll
            for (int jj = 0; jj < 2; jj++)
                mma_f16(Sfc[slot][jj], Ql[s], kf[jj][2 * s], kf[jj][2 * s + 1]);
    };

    auto epiPV = [&](int bb, int g, int slot) {
        float ev[2][4];
        #pragma unroll
        for (int jj = 0; jj < 2; jj++)
            #pragma unroll
            for (int e = 0; e < 4; e++)
                ev[jj][e] = ex2f(Sfc[slot][jj][e]);
        #pragma unroll
        for (int jj = 0; jj < 2; jj++) {
            ls0 += ev[jj][0] + ev[jj][1];
            ls1 += ev[jj][2] + ev[jj][3];
        }
        uint32_t Ph[4], Pl[4];
        split2(ev[0][0], ev[0][1], Ph[0], Pl[0]);
        split2(ev[0][2], ev[0][3], Ph[1], Pl[1]);
        split2(ev[1][0], ev[1][1], Ph[2], Pl[2]);
        split2(ev[1][2], ev[1][3], Ph[3], Pl[3]);
        uint32_t vh[16], vl[16];
        #pragma unroll
        for (int c = 0; c < 4; c++) {
            uint32_t vrow = (uint32_t)(8 * (2 * c + (lt >> 1)) + lr);
            uint32_t aoff = (vrow * PW + 8 * g + 4 * (lt & 1)) * 4;
            ldsm4(vh[4*c], vh[4*c+1], vh[4*c+2], vh[4*c+3],
                  smb + bb + 9216 + aoff);
            ldsm4(vl[4*c], vl[4*c+1], vl[4*c+2], vl[4*c+3],
                  smb + bb + 18432 + aoff);
        }
        #pragma unroll
        for (int jv = 0; jv < 8; jv++) mma_bf16(O[jv], Ph, vh[2 * jv], vh[2 * jv + 1]);
        #pragma unroll
        for (int jv = 0; jv < 8; jv++) mma_bf16(O[jv], Ph, vl[2 * jv], vl[2 * jv + 1]);
        #pragma unroll
        for (int jv = 0; jv < 8; jv++) mma_bf16(O[jv], Pl, vh[2 * jv], vh[2 * jv + 1]);
    };

    for (int ci = 0; ci < S_LEN / 64; ci++) {
        const int bb = (ci & 1) * BUFB;
        if (ci < S_LEN / 64 - 1) loadKV((ci + 1) * 64, bb ^ BUFB);
        issueS(bb, 0, 0);
        #pragma unroll
        for (int g = 0; g < 4; g++) {
            if (g < 3) issueS(bb, g + 1, (g + 1) & 1);
            epiPV(bb, g, g & 1);
        }
        CP_WAIT0();
        __syncthreads();
    }

    // final row-sum reduction; write packed bf16 h/l pairs (O-proj A layout)
    ls0 += __shfl_xor_sync(FULL, ls0, 1);
    ls0 += __shfl_xor_sync(FULL, ls0, 2);
    ls1 += __shfl_xor_sync(FULL, ls1, 1);
    ls1 += __shfl_xor_sync(FULL, ls1, 2);
    float inv0 = 1.f / ls0, inv1 = 1.f / ls1;
    int row0 = q0 + warp * 16 + gl;
    #pragma unroll
    for (int j = 0; j < 8; j++) {
        int colw = (head * DKV + j * 8 + 2 * q) / 2;
        uint32_t h, l;
        split2(O[j][0] * inv0, O[j][1] * inv0, h, l);
        oh[(size_t)row0 * 512 + colw] = h;
        ol[(size_t)row0 * 512 + colw] = l;
        split2(O[j][2] * inv1, O[j][3] * inv1, h, l);
        oh[(size_t)(row0 + 8) * 512 + colw] = h;
        ol[(size_t)(row0 + 8) * 512 + colw] = l;
    }
}

// ---------------- launch ----------------------------------------------------
extern "C" void kernel_launch(void* const* d_in, const int* in_sizes, int n_in,
                              void* d_out, int out_size)
{
    const float* q  = (const float*)d_in[0];
    const float* k  = (const float*)d_in[1];
    const float* v  = (const float*)d_in[2];
    const float* Wq = (const float*)d_in[3];
    const float* bq = (const float*)d_in[4];
    const float* Wk = (const float*)d_in[5];
    const float* bk = (const float*)d_in[6];
    const float* Wv = (const float*)d_in[7];
    const float* bv = (const float*)d_in[8];
    const float* Wo = (const float*)d_in[9];
    const float* bo = (const float*)d_in[10];
    float* out = (float*)d_out;

    void* p;
    cudaGetSymbolAddress(&p, g_wqh);  uint32_t* wqh = (uint32_t*)p;
    cudaGetSymbolAddress(&p, g_wql);  uint32_t* wql = (uint32_t*)p;
    cudaGetSymbolAddress(&p, g_wkh);  uint32_t* wkh = (uint32_t*)p;
    cudaGetSymbolAddress(&p, g_wkl);  uint32_t* wkl = (uint32_t*)p;
    cudaGetSymbolAddress(&p, g_wvh);  uint32_t* wvh = (uint32_t*)p;
    cudaGetSymbolAddress(&p, g_wvl);  uint32_t* wvl = (uint32_t*)p;
    cudaGetSymbolAddress(&p, g_woh);  uint32_t* woh = (uint32_t*)p;
    cudaGetSymbolAddress(&p, g_wol);  uint32_t* wol = (uint32_t*)p;
    cudaGetSymbolAddress(&p, g_qph);  uint32_t* qph = (uint32_t*)p;
    cudaGetSymbolAddress(&p, g_qpl);  uint32_t* qpl = (uint32_t*)p;
    cudaGetSymbolAddress(&p, g_kp);   uint32_t* kpp = (uint32_t*)p;
    cudaGetSymbolAddress(&p, g_vth);  uint32_t* vth = (uint32_t*)p;
    cudaGetSymbolAddress(&p, g_vtl);  uint32_t* vtl = (uint32_t*)p;
    cudaGetSymbolAddress(&p, g_oh);   uint32_t* oh  = (uint32_t*)p;
    cudaGetSymbolAddress(&p, g_ol);   uint32_t* ol  = (uint32_t*)p;

    constexpr int SM_BIG   = (4 * 128 * 20 + 4 * 16 * 136) * 4;  // 75776
    constexpr int SM_SMALL = (4 * 64 * 20 + 4 * 16 * 72) * 4;    // 38912

    cudaFuncSetAttribute((const void*)(bgemm3<128, 128, 32, 2, 4, 4>),
                         cudaFuncAttributeMaxDynamicSharedMemorySize, SM_BIG);
    cudaFuncSetAttribute((const void*)(bgemm3<128, 128, 32, 2, 4, 5>),
                         cudaFuncAttributeMaxDynamicSharedMemorySize, SM_BIG);
    cudaFuncSetAttribute((const void*)(bgemm3<64, 64, 32, 2, 4, 3>),
                         cudaFuncAttributeMaxDynamicSharedMemorySize, SM_SMALL);
    cudaFuncSetAttribute((const void*)mqa_attn_c,
                         cudaFuncAttributeMaxDynamicSharedMemorySize, ATTN_SMEM);

    // weight pre-split
    splitAll<<<(2 * 512 * 1024 + 2 * 512 * 64 + 255) / 256, 256>>>(
        Wq, Wo, Wk, Wv, wqh, wql, woh, wol, wkh, wkl, wvh, wvl);

    // Q projection (fp16 h/l, log2e-scaled epilogue)
    bgemm3<128, 128, 32, 2, 4, 4>
        <<<dim3(DMODEL / 128, S_LEN / 128), 256, SM_BIG>>>(
            q, wqh, wql, bq, nullptr, qph, qpl,
            nullptr, nullptr, nullptr, nullptr, nullptr, nullptr,
            S_LEN, DMODEL, DMODEL);
    // K + V projections fused
    bgemm3<64, 64, 32, 2, 4, 3>
        <<<dim3(2, S_LEN / 64), 256, SM_SMALL>>>(
            k, wkh, wkl, bk, nullptr, kpp, nullptr,
            v, wvh, wvl, bv, vth, vtl,
            S_LEN, DKV, DMODEL);
    // attention -> packed bf16 h/l output
    mqa_attn_c<<<dim3(S_LEN / 128, HEADS), 256, ATTN_SMEM>>>(qph, qpl, kpp,
                                                             vth, vtl, oh, ol);
    // O projection (pre-split A via cp.async)
    bgemm3<128, 128, 32, 2, 4, 5>
        <<<dim3(DMODEL / 128, S_LEN / 128), 256, SM_BIG>>>(
            nullptr, woh, wol, bo, out, nullptr, nullptr,
            nullptr, oh, ol, nullptr, nullptr, nullptr,
            S_LEN, DMODEL, DMODEL);
}

// round 15
// speedup vs baseline: 1.3405x; 1.2865x over previous
#include <cuda_runtime.h>
#include <cstdint>

#define S_LEN   4096
#define DMODEL  1024
#define HEADS   16
#define DKV     64
#define LOG2E   1.4426950408889634f

// ---------------- scratch ---------------------------------------------------
__device__ uint32_t g_wqh[512 * 1024], g_wql[512 * 1024];
__device__ uint32_t g_wkh[512 * 64],   g_wkl[512 * 64];
__device__ uint32_t g_wvh[512 * 64],   g_wvl[512 * 64];
__device__ uint32_t g_woh[512 * 1024], g_wol[512 * 1024];
__device__ uint32_t g_qph[S_LEN * 512], g_qpl[S_LEN * 512];   // fp16 pairs (scaled by log2e)
__device__ uint32_t g_kp[S_LEN * 32];                          // fp16 pairs [key][dk-pair]
__device__ uint32_t g_vt[64 * (S_LEN / 2)];                    // fp16 [dk][key-pair]
__device__ uint32_t g_oh[S_LEN * 512], g_ol[S_LEN * 512];      // attn out, bf16 h/l pairs

// ---------------- numeric helpers -------------------------------------------
__device__ __forceinline__ void split2(float x, float y, uint32_t& h, uint32_t& l) {
    uint32_t hp;
    asm("cvt.rn.bf16x2.f32 %0,%1,%2;" : "=r"(hp) : "f"(y), "f"(x));
    float hx = __uint_as_float(hp << 16);
    float hy = __uint_as_float(hp & 0xffff0000u);
    asm("cvt.rn.bf16x2.f32 %0,%1,%2;" : "=r"(l) : "f"(y - hy), "f"(x - hx));
    h = hp;
}
__device__ __forceinline__ void splitf16(float x, float y, uint32_t& h, uint32_t& l) {
    uint32_t hp;
    asm("cvt.rn.f16x2.f32 %0,%1,%2;" : "=r"(hp) : "f"(y), "f"(x));
    float hx, hy;
    asm("{.reg .f16 a,b; mov.b32 {a,b},%2; cvt.f32.f16 %0,a; cvt.f32.f16 %1,b;}"
        : "=f"(hx), "=f"(hy) : "r"(hp));
    asm("cvt.rn.f16x2.f32 %0,%1,%2;" : "=r"(l) : "f"(y - hy), "f"(x - hx));
    h = hp;
}
__device__ __forceinline__ uint32_t packf16(float x, float y) {
    uint32_t r;
    asm("cvt.rn.f16x2.f32 %0,%1,%2;" : "=r"(r) : "f"(y), "f"(x));
    return r;
}
__device__ __forceinline__ float ex2f(float x) {
    float r;
    asm("ex2.approx.f32 %0,%1;" : "=f"(r) : "f"(x));
    return r;
}
__device__ __forceinline__ void mma_bf16(float* d, const uint32_t* a,
                                         uint32_t b0, uint32_t b1) {
    asm volatile("mma.sync.aligned.m16n8k16.row.col.f32.bf16.bf16.f32 "
        "{%0,%1,%2,%3},{%4,%5,%6,%7},{%8,%9},{%0,%1,%2,%3};"
        : "+f"(d[0]), "+f"(d[1]), "+f"(d[2]), "+f"(d[3])
        : "r"(a[0]), "r"(a[1]), "r"(a[2]), "r"(a[3]), "r"(b0), "r"(b1));
}
__device__ __forceinline__ void mma_f16(float* d, const uint32_t* a,
                                        uint32_t b0, uint32_t b1) {
    asm volatile("mma.sync.aligned.m16n8k16.row.col.f32.f16.f16.f32 "
        "{%0,%1,%2,%3},{%4,%5,%6,%7},{%8,%9},{%0,%1,%2,%3};"
        : "+f"(d[0]), "+f"(d[1]), "+f"(d[2]), "+f"(d[3])
        : "r"(a[0]), "r"(a[1]), "r"(a[2]), "r"(a[3]), "r"(b0), "r"(b1));
}
__device__ __forceinline__ void ldsm4(uint32_t& r0, uint32_t& r1,
                                      uint32_t& r2, uint32_t& r3, uint32_t addr) {
    asm volatile("ldmatrix.sync.aligned.m8n8.x4.shared.b16 {%0,%1,%2,%3}, [%4];"
                 : "=r"(r0), "=r"(r1), "=r"(r2), "=r"(r3) : "r"(addr));
}
__device__ __forceinline__ uint32_t smem_u32(const void* p) {
    uint32_t a;
    asm("{ .reg .u64 t; cvta.to.shared.u64 t, %1; cvt.u32.u64 %0, t; }"
        : "=r"(a) : "l"(p));
    return a;
}
__device__ __forceinline__ void cp16(uint32_t saddr, const void* g) {
    asm volatile("cp.async.cg.shared.global [%0], [%1], 16;" :: "r"(saddr), "l"(g));
}
#define CP_COMMIT() asm volatile("cp.async.commit_group;" ::: "memory")
#define CP_WAIT0()  asm volatile("cp.async.wait_group 0;"  ::: "memory")

// ---------------- combined weight pre-split (bf16 h/l for GEMM B) -----------
__global__ __launch_bounds__(256)
void splitAll(const float* __restrict__ Wq, const float* __restrict__ Wo,
              const float* __restrict__ Wk, const float* __restrict__ Wv,
              uint32_t* __restrict__ wqh, uint32_t* __restrict__ wql,
              uint32_t* __restrict__ woh, uint32_t* __restrict__ wol,
              uint32_t* __restrict__ wkh, uint32_t* __restrict__ wkl,
              uint32_t* __restrict__ wvh, uint32_t* __restrict__ wvl)
{
    constexpr int BIG = 512 * 1024, SMALL = 512 * 64;
    int idx = blockIdx.x * 256 + threadIdx.x;
    const float* W; uint32_t *Wh, *Wl; int i, N;
    if (idx < BIG)               { W = Wq; Wh = wqh; Wl = wql; i = idx;            N = 1024; }
    else if (idx < 2 * BIG)      { W = Wo; Wh = woh; Wl = wol; i = idx - BIG;      N = 1024; }
    else if (idx < 2 * BIG + SMALL) { W = Wk; Wh = wkh; Wl = wkl; i = idx - 2*BIG; N = 64; }
    else if (idx < 2 * BIG + 2 * SMALL) { W = Wv; Wh = wvh; Wl = wvl; i = idx - 2*BIG - SMALL; N = 64; }
    else return;
    int kp = i / N, n = i - kp * N;
    float a = W[(size_t)(2 * kp) * N + n];
    float b = W[(size_t)(2 * kp + 1) * N + n];
    uint32_t h, l;
    split2(a, b, h, l);
    Wh[i] = h; Wl[i] = l;
}

// ---------------- bf16x3 GEMM, cp.async double-buffered, LDSM A -------------
// CMODE 0: fp32 A, fp32 C.  CMODE 3: fused K/V proj (K fp16 pairs / V fp16 T).
// CMODE 4: Q-proj (LOG2E, fp16 h/l).  CMODE 5: pre-split A via Bh2/Bl2, fp32 C.
template<int BM, int BN, int BK, int WARPS_M, int WARPS_N, int CMODE>
__global__ __launch_bounds__(WARPS_M * WARPS_N * 32)
void bgemm3(const float* __restrict__ A, const uint32_t* __restrict__ Bh,
            const uint32_t* __restrict__ Bl, const float* __restrict__ bias,
            float* __restrict__ C, uint32_t* __restrict__ Ch,
            uint32_t* __restrict__ Cl,
            const float* __restrict__ A2, const uint32_t* __restrict__ Bh2,
            const uint32_t* __restrict__ Bl2, const float* __restrict__ bias2,
            uint32_t* __restrict__ Ch2, uint32_t* __restrict__ Cl2,
            int M, int N, int K)
{
    constexpr int THREADS = WARPS_M * WARPS_N * 32;
    constexpr int WM = BM / WARPS_M, WN = BN / WARPS_N;
    constexpr int MT = WM / 16, NT = WN / 8;
    constexpr int KW = BK / 2;
    constexpr int AW = KW + 4;
    constexpr int BW = BN + 8;
    constexpr int ASZ = BM * AW;
    constexpr int BSZ = KW * BW;
    constexpr int A_IT = BM * BK / (4 * THREADS);
    constexpr int B_IT = KW * (BN / 4) / THREADS;
    constexpr bool PRE_A = (CMODE == 5);

    extern __shared__ uint32_t smw[];
    uint32_t* AshB = smw;
    uint32_t* AslB = smw + 2 * ASZ;
    uint32_t* BshB = smw + 4 * ASZ;
    uint32_t* BslB = smw + 4 * ASZ + 2 * BSZ;
    const uint32_t sm_base = smem_u32(smw);
    const uint32_t sm_ash = sm_base;
    const uint32_t sm_asl = sm_base + (uint32_t)(2 * ASZ * 4);
    const uint32_t sm_bsh = smem_u32(BshB);
    const uint32_t sm_bsl = smem_u32(BslB);

    bool isV = false;
    if constexpr (CMODE == 3) {
        if (blockIdx.x == 1) {
            isV = true;
            A = A2; Bh = Bh2; Bl = Bl2; bias = bias2; Ch = Ch2; Cl = Cl2;
        }
    }

    const int tid  = threadIdx.x;
    const int warp = tid >> 5, lane = tid & 31;
    const int g = lane >> 2, q = lane & 3;
    const int lt = lane >> 3, lr = lane & 7;
    const int wm = warp / WARPS_N, wn = warp % WARPS_N;
    const int m0 = blockIdx.y * BM;
    const int n0 = (CMODE == 3) ? 0 : blockIdx.x * BN;

    float acc[MT][NT][4];
    #pragma unroll
    for (int i = 0; i < MT; i++)
        #pragma unroll
        for (int j = 0; j < NT; j++)
            #pragma unroll
            for (int e = 0; e < 4; e++) acc[i][j][e] = 0.f;

    float4 aPF[PRE_A ? 1 : A_IT];

    auto loadA = [&](int k0) {
        if constexpr (!PRE_A) {
            #pragma unroll
            for (int i = 0; i < A_IT; i++) {
                int flat = tid + i * THREADS;
                int r = flat / (BK / 4), c = (flat % (BK / 4)) * 4;
                aPF[i] = *(const float4*)(A + (size_t)(m0 + r) * K + k0 + c);
            }
        }
    };
    auto cpA = [&](int k0, int b) {
        if constexpr (PRE_A) {
            int kp0 = k0 / 2;
            #pragma unroll
            for (int i = 0; i < BM * KW / (4 * THREADS); i++) {
                int flat = tid + i * THREADS;
                int r = flat / (KW / 4), c = (flat % (KW / 4)) * 4;
                uint32_t off = (uint32_t)((b * ASZ + r * AW + c) * 4);
                cp16(sm_ash + off, Bh2 + (size_t)(m0 + r) * (K / 2) + kp0 + c);
                cp16(sm_asl + off, Bl2 + (size_t)(m0 + r) * (K / 2) + kp0 + c);
            }
        }
    };
    auto cpB = [&](int k0, int b) {
        int kp0 = k0 / 2;
        #pragma unroll
        for (int i = 0; i < B_IT; i++) {
            int flat = tid + i * THREADS;
            int kp2 = flat / (BN / 4), c = (flat % (BN / 4)) * 4;
            uint32_t off = (uint32_t)((b * BSZ + kp2 * BW + c) * 4);
            cp16(sm_bsh + off, Bh + (size_t)(kp0 + kp2) * N + n0 + c);
            cp16(sm_bsl + off, Bl + (size_t)(kp0 + kp2) * N + n0 + c);
        }
        CP_COMMIT();
    };
    auto storeA = [&](int b) {
        if constexpr (!PRE_A) {
            uint32_t* Ash = AshB + b * ASZ;
            uint32_t* Asl = AslB + b * ASZ;
            #pragma unroll
            for (int i = 0; i < A_IT; i++) {
                int flat = tid + i * THREADS;
                int r = flat / (BK / 4), c = (flat % (BK / 4)) * 4;
                uint32_t h0, l0, h1, l1;
                split2(aPF[i].x, aPF[i].y, h0, l0);
                split2(aPF[i].z, aPF[i].w, h1, l1);
                Ash[r * AW + c / 2] = h0; Ash[r * AW + c / 2 + 1] = h1;
                Asl[r * AW + c / 2] = l0; Asl[r * AW + c / 2 + 1] = l1;
            }
        }
    };

    loadA(0);
    cpA(0, 0);
    cpB(0, 0);
    storeA(0);
    CP_WAIT0();
    __syncthreads();

    for (int k0 = 0; k0 < K; k0 += BK) {
        const int b = (k0 / BK) & 1;
        const bool more = (k0 + BK < K);
        if (more) { loadA(k0 + BK); cpA(k0 + BK, b ^ 1); cpB(k0 + BK, b ^ 1); }

        const uint32_t ash_b = sm_ash + (uint32_t)((b * ASZ) * 4);
        const uint32_t asl_b = sm_asl + (uint32_t)((b * ASZ) * 4);
        const uint32_t* Bsh = BshB + b * BSZ;
        const uint32_t* Bsl = BslB + b * BSZ;

        #pragma unroll
        for (int kk = 0; kk < 2; kk++) {
            const int wof = kk * 8;
            uint32_t Ah[MT][4], Al[MT][4], Bfh[NT][2], Bfl[NT][2];
            #pragma unroll
            for (int i = 0; i < MT; i++) {
                int mr = wm * WM + i * 16;
                uint32_t aoff = (uint32_t)(((mr + 8 * (lt & 1) + lr) * AW
                                           + wof + 4 * (lt >> 1)) * 4);
                ldsm4(Ah[i][0], Ah[i][1], Ah[i][2], Ah[i][3], ash_b + aoff);
                ldsm4(Al[i][0], Al[i][1], Al[i][2], Al[i][3], asl_b + aoff);
            }
            #pragma unroll
            for (int j = 0; j < NT; j++) {
                int nc = wn * WN + j * 8 + g;
                Bfh[j][0] = Bsh[(wof + q) * BW + nc];
                Bfh[j][1] = Bsh[(wof + q + 4) * BW + nc];
                Bfl[j][0] = Bsl[(wof + q) * BW + nc];
                Bfl[j][1] = Bsl[(wof + q + 4) * BW + nc];
            }
            #pragma unroll
            for (int i = 0; i < MT; i++)
                #pragma unroll
                for (int j = 0; j < NT; j++)
                    mma_bf16(acc[i][j], Ah[i], Bfh[j][0], Bfh[j][1]);
            #pragma unroll
            for (int i = 0; i < MT; i++)
                #pragma unroll
                for (int j = 0; j < NT; j++)
                    mma_bf16(acc[i][j], Ah[i], Bfl[j][0], Bfl[j][1]);
            #pragma unroll
            for (int i = 0; i < MT; i++)
                #pragma unroll
                for (int j = 0; j < NT; j++)
                    mma_bf16(acc[i][j], Al[i], Bfh[j][0], Bfh[j][1]);
        }

        if (more) storeA(b ^ 1);
        CP_WAIT0();
        __syncthreads();
    }

    const unsigned FULL = 0xffffffffu;
    #pragma unroll
    for (int i = 0; i < MT; i++) {
        int row0 = m0 + wm * WM + i * 16 + g;
        #pragma unroll
        for (int j = 0; j < NT; j++) {
            int col = n0 + wn * WN + j * 8 + 2 * q;
            float bx = bias[col], by = bias[col + 1];
            float v0 = acc[i][j][0] + bx, v1 = acc[i][j][1] + by;
            float v2 = acc[i][j][2] + bx, v3 = acc[i][j][3] + by;
            if constexpr (CMODE == 0 || CMODE == 5) {
                float2 w0 = { v0, v1 }, w1 = { v2, v3 };
                *(float2*)(C + (size_t)row0 * N + col) = w0;
                *(float2*)(C + (size_t)(row0 + 8) * N + col) = w1;
            } else if constexpr (CMODE == 4) {
                v0 *= LOG2E; v1 *= LOG2E; v2 *= LOG2E; v3 *= LOG2E;
                uint32_t h, l;
                splitf16(v0, v1, h, l);
                Ch[(size_t)row0 * (N / 2) + col / 2] = h;
                Cl[(size_t)row0 * (N / 2) + col / 2] = l;
                splitf16(v2, v3, h, l);
                Ch[(size_t)(row0 + 8) * (N / 2) + col / 2] = h;
                Cl[(size_t)(row0 + 8) * (N / 2) + col / 2] = l;
            } else {
                if (!isV) {
                    Ch[(size_t)row0 * (N / 2) + col / 2] = packf16(v0, v1);
                    Ch[(size_t)(row0 + 8) * (N / 2) + col / 2] = packf16(v2, v3);
                } else {
                    // V-proj: transposed single fp16 key-pairs
                    float p0 = __shfl_xor_sync(FULL, v0, 4);
                    float p1 = __shfl_xor_sync(FULL, v1, 4);
                    float p2 = __shfl_xor_sync(FULL, v2, 4);
                    float p3 = __shfl_xor_sync(FULL, v3, 4);
                    if ((g & 1) == 0) {
                        Ch[(size_t)col * (S_LEN / 2) + row0 / 2] = packf16(v0, p0);
                        Ch[(size_t)col * (S_LEN / 2) + (row0 + 8) / 2] = packf16(v2, p2);
                    } else {
                        Ch[(size_t)(col + 1) * (S_LEN / 2) + (row0 - 1) / 2] = packf16(p1, v1);
                        Ch[(size_t)(col + 1) * (S_LEN / 2) + (row0 + 7) / 2] = packf16(p3, v3);
                    }
                }
            }
        }
    }
}

// ---------------- flash MQA attention (fp16 S + online-max fp16 PV) ---------
// smem: 2 buffers x [K 9216 | V 9216]; QH/QL above.
#define PW   36
#define BUFB 18432
#define QH_OFF 36864
#define QL_OFF 55296
#define ATTN_SMEM 73728

__global__ __launch_bounds__(256, 2)
void mqa_attn_e(const uint32_t* __restrict__ qph, const uint32_t* __restrict__ qpl,
                const uint32_t* __restrict__ kp, const uint32_t* __restrict__ vt,
                uint32_t* __restrict__ oh, uint32_t* __restrict__ ol)
{
    extern __shared__ char smraw[];
    const uint32_t smb = smem_u32(smraw);
    const int tid  = threadIdx.x;
    const int warp = tid >> 5, lane = tid & 31;
    const int gl = lane >> 2, q = lane & 3;
    const int lt = lane >> 3, lr = lane & 7;
    const int head = blockIdx.y;
    const int q0 = blockIdx.x * 128;
    const unsigned FULL = 0xffffffffu;

    // ---- stage packed Q (fp16, pre-scaled by log2e) ----
    #pragma unroll
    for (int i = 0; i < 4; i++) {
        int idx = tid + i * 256;
        int r = idx >> 3, c4 = (idx & 7) * 4;
        *(uint4*)(smraw + QH_OFF + (r * PW + c4) * 4) =
            *(const uint4*)(qph + (size_t)(q0 + r) * 512 + head * 32 + c4);
        *(uint4*)(smraw + QL_OFF + (r * PW + c4) * 4) =
            *(const uint4*)(qpl + (size_t)(q0 + r) * 512 + head * 32 + c4);
    }

    // ---- async K/V chunk load ----
    const int kkey = tid >> 2, kw0 = (tid & 3) * 8;
    auto loadKV = [&](int k0, int bb) {
        uint32_t base = smb + (uint32_t)bb + (kkey * PW + kw0) * 4;
        const uint32_t* ph = kp + (size_t)(k0 + kkey) * 32 + kw0;
        cp16(base,      ph);
        cp16(base + 16, ph + 4);
        const uint32_t* pv = vt + (size_t)kkey * (S_LEN / 2) + (k0 >> 1) + kw0;
        cp16(base + 9216,      pv);
        cp16(base + 9216 + 16, pv + 4);
        CP_COMMIT();
    };

    loadKV(0, 0);
    __syncthreads();

    // ---- Q fragments via ldmatrix ----
    uint32_t Qh[4][4], Ql[4][4];
    {
        uint32_t brow = (uint32_t)(warp * 16 + 8 * (lt & 1) + lr);
        #pragma unroll
        for (int s = 0; s < 4; s++) {
            uint32_t aoff = (brow * PW + 8 * s + 4 * (lt >> 1)) * 4;
            ldsm4(Qh[s][0], Qh[s][1], Qh[s][2], Qh[s][3], smb + QH_OFF + aoff);
            ldsm4(Ql[s][0], Ql[s][1], Ql[s][2], Ql[s][3], smb + QL_OFF + aoff);
        }
    }
    CP_WAIT0();
    __syncthreads();

    float O[8][4];
    #pragma unroll
    for (int j = 0; j < 8; j++)
        #pragma unroll
        for (int e = 0; e < 4; e++) O[j][e] = 0.f;
    float ls0 = 0.f, ls1 = 0.f;
    float m0 = -1e30f, m1 = -1e30f;

    float Sfc[2][2][4];

    auto issueS = [&](int bb, int g, int slot) {
        uint32_t kf[2][8];
        uint32_t krow = (uint32_t)(16 * g + 8 * (lt >> 1) + lr);
        #pragma unroll
        for (int s = 0; s < 4; s++) {
            uint32_t aoff = (krow * PW + 8 * s + 4 * (lt & 1)) * 4;
            ldsm4(kf[0][2*s], kf[0][2*s+1], kf[1][2*s], kf[1][2*s+1],
                  smb + bb + aoff);
        }
        #pragma unroll
        for (int jj = 0; jj < 2; jj++)
            #pragma unroll
            for (int e = 0; e < 4; e++) Sfc[slot][jj][e] = 0.f;
        #pragma unroll
        for (int s = 0; s < 4; s++)
            #pragma unroll
            for (int jj = 0; jj < 2; jj++)
                mma_f16(Sfc[slot][jj], Qh[s], kf[jj][2 * s], kf[jj][2 * s + 1]);
        #pragma unroll
        for (int s = 0; s < 4; s++)
            #pragma unroll
            for (int jj = 0; jj < 2; jj++)
                mma_f16(Sfc[slot][jj], Ql[s], kf[jj][2 * s], kf[jj][2 * s + 1]);
    };

    auto epiPV = [&](int bb, int g, int slot) {
        // per-row chunk-local max (4 values per row, shared across the quad)
        float ml0 = fmaxf(fmaxf(Sfc[slot][0][0], Sfc[slot][0][1]),
                          fmaxf(Sfc[slot][1][0], Sfc[slot][1][1]));
        float ml1 = fmaxf(fmaxf(Sfc[slot][0][2], Sfc[slot][0][3]),
                          fmaxf(Sfc[slot][1][2], Sfc[slot][1][3]));
        ml0 = fmaxf(ml0, __shfl_xor_sync(FULL, ml0, 1));
        ml0 = fmaxf(ml0, __shfl_xor_sync(FULL, ml0, 2));
        ml1 = fmaxf(ml1, __shfl_xor_sync(FULL, ml1, 1));
        ml1 = fmaxf(ml1, __shfl_xor_sync(FULL, ml1, 2));
        if (ml0 > m0 || ml1 > m1) {
            float mn0 = fmaxf(m0, ml0), mn1 = fmaxf(m1, ml1);
            float f0 = ex2f(m0 - mn0), f1 = ex2f(m1 - mn1);
            ls0 *= f0; ls1 *= f1;
            #pragma unroll
            for (int jv = 0; jv < 8; jv++) {
                O[jv][0] *= f0; O[jv][1] *= f0;
                O[jv][2] *= f1; O[jv][3] *= f1;
            }
            m0 = mn0; m1 = mn1;
        }
        float ev[2][4];
        #pragma unroll
        for (int jj = 0; jj < 2; jj++) {
            ev[jj][0] = ex2f(Sfc[slot][jj][0] - m0);
            ev[jj][1] = ex2f(Sfc[slot][jj][1] - m0);
            ev[jj][2] = ex2f(Sfc[slot][jj][2] - m1);
            ev[jj][3] = ex2f(Sfc[slot][jj][3] - m1);
        }
        #pragma unroll
        for (int jj = 0; jj < 2; jj++) {
            ls0 += ev[jj][0] + ev[jj][1];
            ls1 += ev[jj][2] + ev[jj][3];
        }
        uint32_t Pf[4];
        Pf[0] = packf16(ev[0][0], ev[0][1]);
        Pf[1] = packf16(ev[0][2], ev[0][3]);
        Pf[2] = packf16(ev[1][0], ev[1][1]);
        Pf[3] = packf16(ev[1][2], ev[1][3]);
        uint32_t vf[16];
        #pragma unroll
        for (int c = 0; c < 4; c++) {
            uint32_t vrow = (uint32_t)(8 * (2 * c + (lt >> 1)) + lr);
            uint32_t aoff = (vrow * PW + 8 * g + 4 * (lt & 1)) * 4;
            ldsm4(vf[4*c], vf[4*c+1], vf[4*c+2], vf[4*c+3],
                  smb + bb + 9216 + aoff);
        }
        #pragma unroll
        for (int jv = 0; jv < 8; jv++)
            mma_f16(O[jv], Pf, vf[2 * jv], vf[2 * jv + 1]);
    };

    for (int ci = 0; ci < S_LEN / 64; ci++) {
        const int bb = (ci & 1) * BUFB;
        if (ci < S_LEN / 64 - 1) loadKV((ci + 1) * 64, bb ^ BUFB);
        issueS(bb, 0, 0);
        #pragma unroll
        for (int g = 0; g < 4; g++) {
            if (g < 3) issueS(bb, g + 1, (g + 1) & 1);
            epiPV(bb, g, g & 1);
        }
        CP_WAIT0();
        __syncthreads();
    }

    // final row-sum reduction; write packed bf16 h/l pairs (O-proj A layout)
    ls0 += __shfl_xor_sync(FULL, ls0, 1);
    ls0 += __shfl_xor_sync(FULL, ls0, 2);
    ls1 += __shfl_xor_sync(FULL, ls1, 1);
    ls1 += __shfl_xor_sync(FULL, ls1, 2);
    float inv0 = 1.f / ls0, inv1 = 1.f / ls1;
    int row0 = q0 + warp * 16 + gl;
    #pragma unroll
    for (int j = 0; j < 8; j++) {
        int colw = (head * DKV + j * 8 + 2 * q) / 2;
        uint32_t h, l;
        split2(O[j][0] * inv0, O[j][1] * inv0, h, l);
        oh[(size_t)row0 * 512 + colw] = h;
        ol[(size_t)row0 * 512 + colw] = l;
        split2(O[j][2] * inv1, O[j][3] * inv1, h, l);
        oh[(size_t)(row0 + 8) * 512 + colw] = h;
        ol[(size_t)(row0 + 8) * 512 + colw] = l;
    }
}

// ---------------- launch ----------------------------------------------------
extern "C" void kernel_launch(void* const* d_in, const int* in_sizes, int n_in,
                              void* d_out, int out_size)
{
    const float* q  = (const float*)d_in[0];
    const float* k  = (const float*)d_in[1];
    const float* v  = (const float*)d_in[2];
    const float* Wq = (const float*)d_in[3];
    const float* bq = (const float*)d_in[4];
    const float* Wk = (const float*)d_in[5];
    const float* bk = (const float*)d_in[6];
    const float* Wv = (const float*)d_in[7];
    const float* bv = (const float*)d_in[8];
    const float* Wo = (const float*)d_in[9];
    const float* bo = (const float*)d_in[10];
    float* out = (float*)d_out;

    void* p;
    cudaGetSymbolAddress(&p, g_wqh);  uint32_t* wqh = (uint32_t*)p;
    cudaGetSymbolAddress(&p, g_wql);  uint32_t* wql = (uint32_t*)p;
    cudaGetSymbolAddress(&p, g_wkh);  uint32_t* wkh = (uint32_t*)p;
    cudaGetSymbolAddress(&p, g_wkl);  uint32_t* wkl = (uint32_t*)p;
    cudaGetSymbolAddress(&p, g_wvh);  uint32_t* wvh = (uint32_t*)p;
    cudaGetSymbolAddress(&p, g_wvl);  uint32_t* wvl = (uint32_t*)p;
    cudaGetSymbolAddress(&p, g_woh);  uint32_t* woh = (uint32_t*)p;
    cudaGetSymbolAddress(&p, g_wol);  uint32_t* wol = (uint32_t*)p;
    cudaGetSymbolAddress(&p, g_qph);  uint32_t* qph = (uint32_t*)p;
    cudaGetSymbolAddress(&p, g_qpl);  uint32_t* qpl = (uint32_t*)p;
    cudaGetSymbolAddress(&p, g_kp);   uint32_t* kpp = (uint32_t*)p;
    cudaGetSymbolAddress(&p, g_vt);   uint32_t* vtt = (uint32_t*)p;
    cudaGetSymbolAddress(&p, g_oh);   uint32_t* oh  = (uint32_t*)p;
    cudaGetSymbolAddress(&p, g_ol);   uint32_t* ol  = (uint32_t*)p;

    constexpr int SM_BIG   = (4 * 128 * 20 + 4 * 16 * 136) * 4;  // 75776
    constexpr int SM_SMALL = (4 * 64 * 20 + 4 * 16 * 72) * 4;    // 38912

    cudaFuncSetAttribute((const void*)(bgemm3<128, 128, 32, 2, 4, 4>),
                         cudaFuncAttributeMaxDynamicSharedMemorySize, SM_BIG);
    cudaFuncSetAttribute((const void*)(bgemm3<128, 128, 32, 2, 4, 5>),
                         cudaFuncAttributeMaxDynamicSharedMemorySize, SM_BIG);
    cudaFuncSetAttribute((const void*)(bgemm3<64, 64, 32, 2, 4, 3>),
                         cudaFuncAttributeMaxDynamicSharedMemorySize, SM_SMALL);
    cudaFuncSetAttribute((const void*)mqa_attn_e,
                         cudaFuncAttributeMaxDynamicSharedMemorySize, ATTN_SMEM);

    // weight pre-split
    splitAll<<<(2 * 512 * 1024 + 2 * 512 * 64 + 255) / 256, 256>>>(
        Wq, Wo, Wk, Wv, wqh, wql, woh, wol, wkh, wkl, wvh, wvl);

    // Q projection (fp16 h/l, log2e-scaled epilogue)
    bgemm3<128, 128, 32, 2, 4, 4>
        <<<dim3(DMODEL / 128, S_LEN / 128), 256, SM_BIG>>>(
            q, wqh, wql, bq, nullptr, qph, qpl,
            nullptr, nullptr, nullptr, nullptr, nullptr, nullptr,
            S_LEN, DMODEL, DMODEL);
    // K + V projections fused (K fp16 pairs; V transposed single fp16)
    bgemm3<64, 64, 32, 2, 4, 3>
        <<<dim3(2, S_LEN / 64), 256, SM_SMALL>>>(
            k, wkh, wkl, bk, nullptr, kpp, nullptr,
            v, wvh, wvl, bv, vtt, nullptr,
            S_LEN, DKV, DMODEL);
    // attention -> packed bf16 h/l output
    mqa_attn_e<<<dim3(S_LEN / 128, HEADS), 256, ATTN_SMEM>>>(qph, qpl, kpp,
                                                             vtt, oh, ol);
    // O projection (pre-split A via cp.async)
    bgemm3<128, 128, 32, 2, 4, 5>
        <<<dim3(DMODEL / 128, S_LEN / 128), 256, SM_BIG>>>(
            nullptr, woh, wol, bo, out, nullptr, nullptr,
            nullptr, oh, ol, nullptr, nullptr, nullptr,
            S_LEN, DMODEL, DMODEL);
}